// round 3
// baseline (speedup 1.0000x reference)
#include <cuda_runtime.h>
#include <math.h>

// ---------------------------------------------------------------------------
// GPT forward: embed -> 4x[LN, QKV GEMM, causal attn, proj+res, LN, FC1+GELU,
// FC2+res] -> LN -> lm_head (h @ wte^T).  All fp32.
// B=2, S=2048 (4096 tokens), D=512, H=8, HD=64, FF=2048, L=4, V=50257.
// ---------------------------------------------------------------------------

#define NTOK   4096
#define DMODEL 512
#define NLAYER 4
#define NHEAD  8
#define HDIM   64
#define FFDIM  2048
#define SEQ    2048
#define VOCAB  50257

// Scratch (static device globals -- no runtime allocation allowed)
__device__ float g_x[NTOK * DMODEL];        // residual stream   (8 MB)
__device__ float g_h[NTOK * DMODEL];        // LN output         (8 MB)
__device__ float g_qkv[NTOK * 3 * DMODEL];  // qkv               (24 MB)
__device__ float g_o[NTOK * DMODEL];        // attn output       (8 MB)
__device__ float g_ff[NTOK * FFDIM];        // MLP hidden        (32 MB)

// ---------------------------------------------------------------------------
// Embedding: x[tok,d] = wte[idx[tok],d] + wpe[tok%SEQ, d]
// ---------------------------------------------------------------------------
__global__ void embed_kernel(const int* __restrict__ idx,
                             const float* __restrict__ wte,
                             const float* __restrict__ wpe,
                             float* __restrict__ x) {
    int i = blockIdx.x * 256 + threadIdx.x;   // over NTOK*DMODEL
    int tok = i >> 9;                          // / 512
    int d   = i & 511;
    int s   = tok & (SEQ - 1);
    x[i] = wte[(size_t)idx[tok] * DMODEL + d] + wpe[s * DMODEL + d];
}

// ---------------------------------------------------------------------------
// LayerNorm over last dim (512). One block of 256 threads per token row.
// ---------------------------------------------------------------------------
__global__ void ln_kernel(const float* __restrict__ x,
                          const float* __restrict__ w,
                          const float* __restrict__ b,
                          float* __restrict__ out) {
    int row = blockIdx.x;
    int tid = threadIdx.x;
    const float* xr = x + (size_t)row * DMODEL;
    float v0 = xr[tid];
    float v1 = xr[tid + 256];
    float s  = v0 + v1;
    float sq = v0 * v0 + v1 * v1;
    #pragma unroll
    for (int off = 16; off >= 1; off >>= 1) {
        s  += __shfl_xor_sync(0xffffffffu, s,  off);
        sq += __shfl_xor_sync(0xffffffffu, sq, off);
    }
    __shared__ float ss[8], ssq[8];
    int warp = tid >> 5, lane = tid & 31;
    if (lane == 0) { ss[warp] = s; ssq[warp] = sq; }
    __syncthreads();
    float ts = 0.f, tq = 0.f;
    #pragma unroll
    for (int wI = 0; wI < 8; wI++) { ts += ss[wI]; tq += ssq[wI]; }
    float mean = ts * (1.0f / DMODEL);
    float var  = tq * (1.0f / DMODEL) - mean * mean;
    float rstd = rsqrtf(var + 1e-5f);
    float* outr = out + (size_t)row * DMODEL;
    outr[tid]       = (v0 - mean) * rstd * w[tid]       + b[tid];
    outr[tid + 256] = (v1 - mean) * rstd * w[tid + 256] + b[tid + 256];
}

// ---------------------------------------------------------------------------
// SGEMM: C[M,N] = epilogue(A[M,K] @ B(+bias)).
//   TRANSB=false: B is [K,N] row-major (weight matrices, N % 128 == 0).
//   TRANSB=true : B is [N,K] row-major (lm_head: wte), N guarded.
// EPI: 0 = +bias; 1 = gelu(+bias); 2 = +bias + residual R; 3 = none.
// Tiles 128x128x8, 256 threads, 8x8 per thread.
// Thread n-columns strided (n = n0 + tx + 16*j) for coalesced epilogue.
// ---------------------------------------------------------------------------
#define EPI_BIAS 0
#define EPI_GELU 1
#define EPI_RES  2
#define EPI_NONE 3

template<bool TRANSB, int EPI>
__global__ __launch_bounds__(256)
void gemm_kernel(const float* __restrict__ A, const float* __restrict__ B,
                 const float* __restrict__ bias, const float* __restrict__ R,
                 float* __restrict__ C, int M, int N, int K) {
    __shared__ float As[8][128];
    __shared__ float Bs[8][128];

    const int tid = threadIdx.x;
    const int m0  = blockIdx.y * 128;
    const int n0  = blockIdx.x * 128;
    const int tx  = tid & 15;
    const int ty  = tid >> 4;

    // load-index precompute
    const int a_r = tid >> 1;           // 0..127
    const int a_c = (tid & 1) * 4;      // 0 or 4
    const int b_r = tid >> 5;           // 0..7    (non-trans)
    const int b_c = (tid & 31) * 4;     // 0..124  (non-trans)
    const int bt_n = tid >> 1;          // 0..127  (trans)
    const int bt_k = (tid & 1) * 4;     // 0 or 4  (trans)

    float acc[8][8];
    #pragma unroll
    for (int i = 0; i < 8; i++)
        #pragma unroll
        for (int j = 0; j < 8; j++) acc[i][j] = 0.f;

    for (int k0 = 0; k0 < K; k0 += 8) {
        // --- load A tile (transposed into smem) ---
        float4 av = *(const float4*)(A + (size_t)(m0 + a_r) * K + k0 + a_c);
        As[a_c + 0][a_r] = av.x;
        As[a_c + 1][a_r] = av.y;
        As[a_c + 2][a_r] = av.z;
        As[a_c + 3][a_r] = av.w;
        // --- load B tile ---
        if (!TRANSB) {
            float4 bv = *(const float4*)(B + (size_t)(k0 + b_r) * N + n0 + b_c);
            *(float4*)&Bs[b_r][b_c] = bv;
        } else {
            int n = n0 + bt_n;
            float4 bv = make_float4(0.f, 0.f, 0.f, 0.f);
            if (n < N) bv = *(const float4*)(B + (size_t)n * K + k0 + bt_k);
            Bs[bt_k + 0][bt_n] = bv.x;
            Bs[bt_k + 1][bt_n] = bv.y;
            Bs[bt_k + 2][bt_n] = bv.z;
            Bs[bt_k + 3][bt_n] = bv.w;
        }
        __syncthreads();
        // --- compute ---
        #pragma unroll
        for (int k = 0; k < 8; k++) {
            float a[8], b[8];
            *(float4*)&a[0] = *(const float4*)&As[k][ty * 8];
            *(float4*)&a[4] = *(const float4*)&As[k][ty * 8 + 4];
            #pragma unroll
            for (int j = 0; j < 8; j++) b[j] = Bs[k][tx + 16 * j];
            #pragma unroll
            for (int i = 0; i < 8; i++)
                #pragma unroll
                for (int j = 0; j < 8; j++)
                    acc[i][j] = fmaf(a[i], b[j], acc[i][j]);
        }
        __syncthreads();
    }

    // --- epilogue ---
    #pragma unroll
    for (int i = 0; i < 8; i++) {
        int m = m0 + ty * 8 + i;
        size_t rowoff = (size_t)m * N;
        #pragma unroll
        for (int j = 0; j < 8; j++) {
            int n = n0 + tx + 16 * j;
            if (n < N) {
                float v = acc[i][j];
                if (EPI != EPI_NONE) v += bias[n];
                if (EPI == EPI_GELU)
                    v = 0.5f * v * (1.0f + erff(v * 0.70710678118654752f));
                if (EPI == EPI_RES)
                    v += R[rowoff + n];
                C[rowoff + n] = v;
            }
        }
    }
}

// ---------------------------------------------------------------------------
// Causal flash attention, fp32. One block per (q-tile of 64, head, batch).
// 256 threads. Tiles 64x64, HD=64. Online softmax, P round-tripped via smem.
// Dynamic smem: QsT,KsT,Vs,PsT = 4 * 64*64 floats = 64 KB.
// ---------------------------------------------------------------------------
__global__ __launch_bounds__(256)
void attn_kernel(const float* __restrict__ qkv, float* __restrict__ o) {
    extern __shared__ float sm[];
    float* QsT = sm;                // [hd][row]
    float* KsT = sm + 4096;        // [hd][col]
    float* Vs  = sm + 8192;        // [row][hd]
    float* PsT = sm + 12288;       // [col][row]

    const int tid = threadIdx.x;
    const int qb  = blockIdx.x;
    const int hh  = blockIdx.y;
    const int bb  = blockIdx.z;
    const int q0  = qb * 64;
    const size_t base = (size_t)(bb * SEQ) * (3 * DMODEL) + hh * HDIM;

    // load Q tile transposed: 64 rows x 64 dims
    {
        int r  = tid >> 2;
        int d0 = (tid & 3) * 16;
        const float* src = qkv + base + (size_t)(q0 + r) * (3 * DMODEL) + d0;
        #pragma unroll
        for (int u = 0; u < 4; u++) {
            float4 v = *(const float4*)(src + u * 4);
            int d = d0 + u * 4;
            QsT[(d + 0) * 64 + r] = v.x;
            QsT[(d + 1) * 64 + r] = v.y;
            QsT[(d + 2) * 64 + r] = v.z;
            QsT[(d + 3) * 64 + r] = v.w;
        }
    }

    const int tx = tid & 15;
    const int ty = tid >> 4;

    float m_i[4], l_i[4], oacc[4][4];
    #pragma unroll
    for (int i = 0; i < 4; i++) {
        m_i[i] = -1e30f;
        l_i[i] = 0.f;
        #pragma unroll
        for (int j = 0; j < 4; j++) oacc[i][j] = 0.f;
    }

    for (int kb = 0; kb <= qb; kb++) {
        const int k0 = kb * 64;
        __syncthreads();   // prev PV done with Vs/PsT; Q visible (1st iter)
        // load K (transposed) and V tiles
        {
            int r  = tid >> 2;
            int d0 = (tid & 3) * 16;
            const float* ksrc = qkv + base + DMODEL     + (size_t)(k0 + r) * (3 * DMODEL) + d0;
            const float* vsrc = qkv + base + 2 * DMODEL + (size_t)(k0 + r) * (3 * DMODEL) + d0;
            #pragma unroll
            for (int u = 0; u < 4; u++) {
                float4 kv = *(const float4*)(ksrc + u * 4);
                int d = d0 + u * 4;
                KsT[(d + 0) * 64 + r] = kv.x;
                KsT[(d + 1) * 64 + r] = kv.y;
                KsT[(d + 2) * 64 + r] = kv.z;
                KsT[(d + 3) * 64 + r] = kv.w;
                float4 vv = *(const float4*)(vsrc + u * 4);
                *(float4*)&Vs[r * 64 + d] = vv;
            }
        }
        __syncthreads();

        // S = Q @ K^T (4x4 per thread)
        float s[4][4];
        #pragma unroll
        for (int i = 0; i < 4; i++)
            #pragma unroll
            for (int j = 0; j < 4; j++) s[i][j] = 0.f;
        #pragma unroll 8
        for (int k = 0; k < 64; k++) {
            float4 aq = *(const float4*)&QsT[k * 64 + ty * 4];
            float4 bk = *(const float4*)&KsT[k * 64 + tx * 4];
            float a[4] = {aq.x, aq.y, aq.z, aq.w};
            float b[4] = {bk.x, bk.y, bk.z, bk.w};
            #pragma unroll
            for (int i = 0; i < 4; i++)
                #pragma unroll
                for (int j = 0; j < 4; j++)
                    s[i][j] = fmaf(a[i], b[j], s[i][j]);
        }

        const float scale = 0.125f;   // 1/sqrt(64)
        const bool diag = (kb == qb);
        #pragma unroll
        for (int i = 0; i < 4; i++) {
            int qg = q0 + ty * 4 + i;
            #pragma unroll
            for (int j = 0; j < 4; j++) {
                s[i][j] *= scale;
                if (diag && (k0 + tx * 4 + j) > qg) s[i][j] = -1e30f;
            }
        }

        // online softmax per row (row owned by 16 lanes sharing ty)
        #pragma unroll
        for (int i = 0; i < 4; i++) {
            float rmax = fmaxf(fmaxf(s[i][0], s[i][1]), fmaxf(s[i][2], s[i][3]));
            #pragma unroll
            for (int off = 1; off < 16; off <<= 1)
                rmax = fmaxf(rmax, __shfl_xor_sync(0xffffffffu, rmax, off));
            float newm = fmaxf(m_i[i], rmax);
            float corr = __expf(m_i[i] - newm);
            float rsum = 0.f;
            #pragma unroll
            for (int j = 0; j < 4; j++) {
                s[i][j] = __expf(s[i][j] - newm);
                rsum += s[i][j];
            }
            #pragma unroll
            for (int off = 1; off < 16; off <<= 1)
                rsum += __shfl_xor_sync(0xffffffffu, rsum, off);
            l_i[i] = l_i[i] * corr + rsum;
            m_i[i] = newm;
            #pragma unroll
            for (int j = 0; j < 4; j++) {
                oacc[i][j] *= corr;
                PsT[(tx * 4 + j) * 64 + ty * 4 + i] = s[i][j];
            }
        }
        __syncthreads();

        // O += P @ V
        #pragma unroll 8
        for (int j = 0; j < 64; j++) {
            float4 pv = *(const float4*)&PsT[j * 64 + ty * 4];
            float4 vv = *(const float4*)&Vs[j * 64 + tx * 4];
            float p[4] = {pv.x, pv.y, pv.z, pv.w};
            float v[4] = {vv.x, vv.y, vv.z, vv.w};
            #pragma unroll
            for (int i = 0; i < 4; i++)
                #pragma unroll
                for (int jj = 0; jj < 4; jj++)
                    oacc[i][jj] = fmaf(p[i], v[jj], oacc[i][jj]);
        }
    }

    // finalize + store (heads interleaved in D)
    #pragma unroll
    for (int i = 0; i < 4; i++) {
        float inv = 1.0f / l_i[i];
        size_t row = (size_t)(bb * SEQ + q0 + ty * 4 + i) * DMODEL + hh * HDIM;
        #pragma unroll
        for (int j = 0; j < 4; j++)
            o[row + tx * 4 + j] = oacc[i][j] * inv;
    }
}

// ---------------------------------------------------------------------------
// Host orchestration (graph-capturable: kernel launches only)
// ---------------------------------------------------------------------------
extern "C" void kernel_launch(void* const* d_in, const int* in_sizes, int n_in,
                              void* d_out, int out_size) {
    const int*   idx   = (const int*)d_in[0];
    const float* wte   = (const float*)d_in[1];
    const float* wpe   = (const float*)d_in[2];
    const float* ln1_w = (const float*)d_in[3];
    const float* ln1_b = (const float*)d_in[4];
    const float* Wqkv  = (const float*)d_in[5];
    const float* bqkv  = (const float*)d_in[6];
    const float* Wproj = (const float*)d_in[7];
    const float* bproj = (const float*)d_in[8];
    const float* ln2_w = (const float*)d_in[9];
    const float* ln2_b = (const float*)d_in[10];
    const float* Wfc   = (const float*)d_in[11];
    const float* bfc   = (const float*)d_in[12];
    const float* Wfc2  = (const float*)d_in[13];
    const float* bfc2  = (const float*)d_in[14];
    const float* lnf_w = (const float*)d_in[15];
    const float* lnf_b = (const float*)d_in[16];
    float* out = (float*)d_out;

    float *x, *h, *qkv, *o, *ff;
    cudaGetSymbolAddress((void**)&x,   g_x);
    cudaGetSymbolAddress((void**)&h,   g_h);
    cudaGetSymbolAddress((void**)&qkv, g_qkv);
    cudaGetSymbolAddress((void**)&o,   g_o);
    cudaGetSymbolAddress((void**)&ff,  g_ff);

    cudaFuncSetAttribute(attn_kernel,
                         cudaFuncAttributeMaxDynamicSharedMemorySize, 65536);

    embed_kernel<<<(NTOK * DMODEL) / 256, 256>>>(idx, wte, wpe, x);

    for (int l = 0; l < NLAYER; l++) {
        const float* wq  = Wqkv  + (size_t)l * DMODEL * 3 * DMODEL;
        const float* bq  = bqkv  + (size_t)l * 3 * DMODEL;
        const float* wp  = Wproj + (size_t)l * DMODEL * DMODEL;
        const float* bp  = bproj + (size_t)l * DMODEL;
        const float* wf1 = Wfc   + (size_t)l * DMODEL * FFDIM;
        const float* bf1 = bfc   + (size_t)l * FFDIM;
        const float* wf2 = Wfc2  + (size_t)l * FFDIM * DMODEL;
        const float* bf2 = bfc2  + (size_t)l * DMODEL;

        ln_kernel<<<NTOK, 256>>>(x, ln1_w + l * DMODEL, ln1_b + l * DMODEL, h);

        gemm_kernel<false, EPI_BIAS><<<dim3((3 * DMODEL) / 128, NTOK / 128), 256>>>(
            h, wq, bq, nullptr, qkv, NTOK, 3 * DMODEL, DMODEL);

        attn_kernel<<<dim3(SEQ / 64, NHEAD, NTOK / SEQ), 256, 65536>>>(qkv, o);

        gemm_kernel<false, EPI_RES><<<dim3(DMODEL / 128, NTOK / 128), 256>>>(
            o, wp, bp, x, x, NTOK, DMODEL, DMODEL);

        ln_kernel<<<NTOK, 256>>>(x, ln2_w + l * DMODEL, ln2_b + l * DMODEL, h);

        gemm_kernel<false, EPI_GELU><<<dim3(FFDIM / 128, NTOK / 128), 256>>>(
            h, wf1, bf1, nullptr, ff, NTOK, FFDIM, DMODEL);

        gemm_kernel<false, EPI_RES><<<dim3(DMODEL / 128, NTOK / 128), 256>>>(
            ff, wf2, bf2, x, x, NTOK, DMODEL, FFDIM);
    }

    ln_kernel<<<NTOK, 256>>>(x, lnf_w, lnf_b, h);

    // logits = h @ wte^T   [4096, 50257]
    gemm_kernel<true, EPI_NONE><<<dim3((VOCAB + 127) / 128, NTOK / 128), 256>>>(
        h, wte, nullptr, nullptr, out, NTOK, VOCAB, DMODEL);
}

// round 5
// speedup vs baseline: 1.8034x; 1.8034x over previous
#include <cuda_runtime.h>
#include <math.h>
#include <cstdint>

// ---------------------------------------------------------------------------
// GPT forward. GEMMs via warp-level tf32 mma.sync (sm_80 PTX -- compiles on
// plain sm_103 target; tcgen05 is rejected by this harness's ptxas target).
// B=2, S=2048 (4096 tokens), D=512, H=8, HD=64, FF=2048, L=4, V=50257.
// ---------------------------------------------------------------------------

#define NTOK   4096
#define DMODEL 512
#define NLAYER 4
#define NHEAD  8
#define HDIM   64
#define FFDIM  2048
#define SEQ    2048
#define VOCAB  50257

__device__ float g_x[NTOK * DMODEL];
__device__ float g_h[NTOK * DMODEL];
__device__ float g_qkv[NTOK * 3 * DMODEL];
__device__ float g_o[NTOK * DMODEL];
__device__ float g_ff[NTOK * FFDIM];

// ---------------------------------------------------------------------------
// Embedding
// ---------------------------------------------------------------------------
__global__ void embed_kernel(const int* __restrict__ idx,
                             const float* __restrict__ wte,
                             const float* __restrict__ wpe,
                             float* __restrict__ x) {
    int i = blockIdx.x * 256 + threadIdx.x;
    int tok = i >> 9;
    int d   = i & 511;
    int s   = tok & (SEQ - 1);
    x[i] = wte[(size_t)idx[tok] * DMODEL + d] + wpe[s * DMODEL + d];
}

// ---------------------------------------------------------------------------
// LayerNorm over last dim (512)
// ---------------------------------------------------------------------------
__global__ void ln_kernel(const float* __restrict__ x,
                          const float* __restrict__ w,
                          const float* __restrict__ b,
                          float* __restrict__ out) {
    int row = blockIdx.x;
    int tid = threadIdx.x;
    const float* xr = x + (size_t)row * DMODEL;
    float v0 = xr[tid];
    float v1 = xr[tid + 256];
    float s  = v0 + v1;
    float sq = v0 * v0 + v1 * v1;
    #pragma unroll
    for (int off = 16; off >= 1; off >>= 1) {
        s  += __shfl_xor_sync(0xffffffffu, s,  off);
        sq += __shfl_xor_sync(0xffffffffu, sq, off);
    }
    __shared__ float ss[8], ssq[8];
    int warp = tid >> 5, lane = tid & 31;
    if (lane == 0) { ss[warp] = s; ssq[warp] = sq; }
    __syncthreads();
    float ts = 0.f, tq = 0.f;
    #pragma unroll
    for (int wI = 0; wI < 8; wI++) { ts += ss[wI]; tq += ssq[wI]; }
    float mean = ts * (1.0f / DMODEL);
    float var  = tq * (1.0f / DMODEL) - mean * mean;
    float rstd = rsqrtf(var + 1e-5f);
    float* outr = out + (size_t)row * DMODEL;
    outr[tid]       = (v0 - mean) * rstd * w[tid]       + b[tid];
    outr[tid + 256] = (v1 - mean) * rstd * w[tid + 256] + b[tid + 256];
}

// ---------------------------------------------------------------------------
// tf32 helpers
// ---------------------------------------------------------------------------
__device__ __forceinline__ float4 rtf32x4(float4 v) {
    uint32_t a, b, c, d;
    asm("cvt.rna.tf32.f32 %0, %1;" : "=r"(a) : "f"(v.x));
    asm("cvt.rna.tf32.f32 %0, %1;" : "=r"(b) : "f"(v.y));
    asm("cvt.rna.tf32.f32 %0, %1;" : "=r"(c) : "f"(v.z));
    asm("cvt.rna.tf32.f32 %0, %1;" : "=r"(d) : "f"(v.w));
    v.x = __uint_as_float(a); v.y = __uint_as_float(b);
    v.z = __uint_as_float(c); v.w = __uint_as_float(d);
    return v;
}

__device__ __forceinline__ void mma_tf32(float* d, const uint32_t* a,
                                         const uint32_t* b) {
    asm volatile(
        "mma.sync.aligned.m16n8k8.row.col.f32.tf32.tf32.f32 "
        "{%0,%1,%2,%3}, {%4,%5,%6,%7}, {%8,%9}, {%0,%1,%2,%3};"
        : "+f"(d[0]), "+f"(d[1]), "+f"(d[2]), "+f"(d[3])
        : "r"(a[0]), "r"(a[1]), "r"(a[2]), "r"(a[3]),
          "r"(b[0]), "r"(b[1]));
}

// ---------------------------------------------------------------------------
// tf32 mma GEMM: C[M,N] = epi(A[M,K] @ B)
//   TRANSB=false: B is [K,N] row-major (layer weights, N % 128 == 0)
//   TRANSB=true : B is [N,K] row-major (lm_head: wte), N guarded vs VOCAB
// CTA tile 128x128, K chunk 32. 256 threads = 8 warps (2 m x 4 n),
// warp tile 64x32 = 4x4 frags of m16n8k8. Smem [32][136] (conflict-free
// fragment loads). Global prefetch for chunk i+1 overlapped with MMA of i.
// Operands pre-rounded RNA->tf32 (unbiased).
// EPI: 0 bias, 1 bias+gelu, 2 bias+residual, 3 none.
// ---------------------------------------------------------------------------
#define EPI_BIAS 0
#define EPI_GELU 1
#define EPI_RES  2
#define EPI_NONE 3

template<bool TRANSB, int EPI>
__global__ __launch_bounds__(256)
void mma_gemm_kernel(const float* __restrict__ A, const float* __restrict__ B,
                     const float* __restrict__ bias, const float* __restrict__ R,
                     float* __restrict__ C, int M, int N, int K) {
    __shared__ float As[32][136];   // [k][m]
    __shared__ float Bs[32][136];   // [k][n]

    const int tid  = threadIdx.x;
    const int lane = tid & 31;
    const int wid  = tid >> 5;
    const int wm   = wid & 1;          // 0..1
    const int wn   = wid >> 1;         // 0..3
    const int m0   = blockIdx.x * 128;
    const int n0   = blockIdx.y * 128;

    const int tig  = lane & 3;         // thread-in-group
    const int grp  = lane >> 2;        // group id

    float acc[4][4][4];
    #pragma unroll
    for (int i = 0; i < 4; i++)
        #pragma unroll
        for (int j = 0; j < 4; j++)
            #pragma unroll
            for (int r = 0; r < 4; r++) acc[i][j][r] = 0.f;

    // staging index precompute
    const int st_r  = tid >> 1;               // row (m or n) 0..127
    const int st_k0 = (tid & 1) * 16;         // k offset 0 or 16
    const int bq_n  = (tid & 31) * 4;         // non-trans B: n offset
    const int bq_k  = tid >> 5;               // non-trans B: k row base

    const int nchunk = K >> 5;

    float4 pa[4], pb[4];

    // prefetch chunk 0
    {
        const float* Ap = A + (size_t)(m0 + st_r) * K + st_k0;
        #pragma unroll
        for (int u = 0; u < 4; u++)
            pa[u] = *(const float4*)(Ap + u * 4);
        if (!TRANSB) {
            #pragma unroll
            for (int u = 0; u < 4; u++)
                pb[u] = *(const float4*)(B + (size_t)(u * 8 + bq_k) * N + n0 + bq_n);
        } else {
            int n = n0 + st_r;
            if (n < N) {
                const float* Bp = B + (size_t)n * K + st_k0;
                #pragma unroll
                for (int u = 0; u < 4; u++)
                    pb[u] = *(const float4*)(Bp + u * 4);
            } else {
                #pragma unroll
                for (int u = 0; u < 4; u++)
                    pb[u] = make_float4(0.f, 0.f, 0.f, 0.f);
            }
        }
    }

    #pragma unroll 1
    for (int ch = 0; ch < nchunk; ch++) {
        __syncthreads();   // previous compute done with smem
        // store staged chunk (convert to tf32)
        #pragma unroll
        for (int u = 0; u < 4; u++) {
            float4 av = rtf32x4(pa[u]);
            int k = st_k0 + u * 4;
            As[k + 0][st_r] = av.x;
            As[k + 1][st_r] = av.y;
            As[k + 2][st_r] = av.z;
            As[k + 3][st_r] = av.w;
            float4 bv = rtf32x4(pb[u]);
            if (!TRANSB) {
                *(float4*)&Bs[u * 8 + bq_k][bq_n] = bv;
            } else {
                Bs[k + 0][st_r] = bv.x;
                Bs[k + 1][st_r] = bv.y;
                Bs[k + 2][st_r] = bv.z;
                Bs[k + 3][st_r] = bv.w;
            }
        }
        __syncthreads();

        // prefetch next chunk while MMAs run
        if (ch + 1 < nchunk) {
            const int k0 = (ch + 1) * 32;
            const float* Ap = A + (size_t)(m0 + st_r) * K + k0 + st_k0;
            #pragma unroll
            for (int u = 0; u < 4; u++)
                pa[u] = *(const float4*)(Ap + u * 4);
            if (!TRANSB) {
                #pragma unroll
                for (int u = 0; u < 4; u++)
                    pb[u] = *(const float4*)(B + (size_t)(k0 + u * 8 + bq_k) * N + n0 + bq_n);
            } else {
                int n = n0 + st_r;
                if (n < N) {
                    const float* Bp = B + (size_t)n * K + k0 + st_k0;
                    #pragma unroll
                    for (int u = 0; u < 4; u++)
                        pb[u] = *(const float4*)(Bp + u * 4);
                }
            }
        }

        // compute: 4 k-steps of 8
        #pragma unroll
        for (int ks = 0; ks < 4; ks++) {
            const int c = ks * 8 + tig;
            uint32_t af[4][4];
            #pragma unroll
            for (int mf = 0; mf < 4; mf++) {
                int r = wm * 64 + mf * 16 + grp;
                af[mf][0] = __float_as_uint(As[c][r]);
                af[mf][1] = __float_as_uint(As[c][r + 8]);
                af[mf][2] = __float_as_uint(As[c + 4][r]);
                af[mf][3] = __float_as_uint(As[c + 4][r + 8]);
            }
            uint32_t bf[4][2];
            #pragma unroll
            for (int nf = 0; nf < 4; nf++) {
                int n = wn * 32 + nf * 8 + grp;
                bf[nf][0] = __float_as_uint(Bs[c][n]);
                bf[nf][1] = __float_as_uint(Bs[c + 4][n]);
            }
            #pragma unroll
            for (int mf = 0; mf < 4; mf++)
                #pragma unroll
                for (int nf = 0; nf < 4; nf++)
                    mma_tf32(acc[mf][nf], af[mf], bf[nf]);
        }
    }

    // epilogue: c0,c1 at (row, 2*tig), c2,c3 at (row+8, 2*tig)
    #pragma unroll
    for (int mf = 0; mf < 4; mf++) {
        #pragma unroll
        for (int half = 0; half < 2; half++) {
            int row = m0 + wm * 64 + mf * 16 + grp + half * 8;
            size_t ro = (size_t)row * N;
            #pragma unroll
            for (int nf = 0; nf < 4; nf++) {
                int col = n0 + wn * 32 + nf * 8 + tig * 2;
                float v0 = acc[mf][nf][half * 2 + 0];
                float v1 = acc[mf][nf][half * 2 + 1];
                if (EPI != EPI_NONE) { v0 += bias[col]; v1 += bias[col + 1]; }
                if (EPI == EPI_GELU) {
                    v0 = 0.5f * v0 * (1.0f + erff(v0 * 0.70710678118654752f));
                    v1 = 0.5f * v1 * (1.0f + erff(v1 * 0.70710678118654752f));
                }
                if (EPI == EPI_RES) { v0 += R[ro + col]; v1 += R[ro + col + 1]; }
                if (!TRANSB) {
                    C[ro + col]     = v0;
                    C[ro + col + 1] = v1;
                } else {
                    if (col < N)     C[ro + col]     = v0;
                    if (col + 1 < N) C[ro + col + 1] = v1;
                }
            }
        }
    }
}

// ---------------------------------------------------------------------------
// Causal flash attention, fp32 (unchanged — passing since R2)
// ---------------------------------------------------------------------------
__global__ __launch_bounds__(256)
void attn_kernel(const float* __restrict__ qkv, float* __restrict__ o) {
    extern __shared__ float sm[];
    float* QsT = sm;
    float* KsT = sm + 4096;
    float* Vs  = sm + 8192;
    float* PsT = sm + 12288;

    const int tid = threadIdx.x;
    const int qb  = blockIdx.x;
    const int hh  = blockIdx.y;
    const int bb  = blockIdx.z;
    const int q0  = qb * 64;
    const size_t base = (size_t)(bb * SEQ) * (3 * DMODEL) + hh * HDIM;

    {
        int r  = tid >> 2;
        int d0 = (tid & 3) * 16;
        const float* src = qkv + base + (size_t)(q0 + r) * (3 * DMODEL) + d0;
        #pragma unroll
        for (int u = 0; u < 4; u++) {
            float4 v = *(const float4*)(src + u * 4);
            int d = d0 + u * 4;
            QsT[(d + 0) * 64 + r] = v.x;
            QsT[(d + 1) * 64 + r] = v.y;
            QsT[(d + 2) * 64 + r] = v.z;
            QsT[(d + 3) * 64 + r] = v.w;
        }
    }

    const int tx = tid & 15;
    const int ty = tid >> 4;

    float m_i[4], l_i[4], oacc[4][4];
    #pragma unroll
    for (int i = 0; i < 4; i++) {
        m_i[i] = -1e30f;
        l_i[i] = 0.f;
        #pragma unroll
        for (int j = 0; j < 4; j++) oacc[i][j] = 0.f;
    }

    for (int kb = 0; kb <= qb; kb++) {
        const int k0 = kb * 64;
        __syncthreads();
        {
            int r  = tid >> 2;
            int d0 = (tid & 3) * 16;
            const float* ksrc = qkv + base + DMODEL     + (size_t)(k0 + r) * (3 * DMODEL) + d0;
            const float* vsrc = qkv + base + 2 * DMODEL + (size_t)(k0 + r) * (3 * DMODEL) + d0;
            #pragma unroll
            for (int u = 0; u < 4; u++) {
                float4 kv = *(const float4*)(ksrc + u * 4);
                int d = d0 + u * 4;
                KsT[(d + 0) * 64 + r] = kv.x;
                KsT[(d + 1) * 64 + r] = kv.y;
                KsT[(d + 2) * 64 + r] = kv.z;
                KsT[(d + 3) * 64 + r] = kv.w;
                float4 vv = *(const float4*)(vsrc + u * 4);
                *(float4*)&Vs[r * 64 + d] = vv;
            }
        }
        __syncthreads();

        float s[4][4];
        #pragma unroll
        for (int i = 0; i < 4; i++)
            #pragma unroll
            for (int j = 0; j < 4; j++) s[i][j] = 0.f;
        #pragma unroll 8
        for (int k = 0; k < 64; k++) {
            float4 aq = *(const float4*)&QsT[k * 64 + ty * 4];
            float4 bk = *(const float4*)&KsT[k * 64 + tx * 4];
            float a[4] = {aq.x, aq.y, aq.z, aq.w};
            float b[4] = {bk.x, bk.y, bk.z, bk.w};
            #pragma unroll
            for (int i = 0; i < 4; i++)
                #pragma unroll
                for (int j = 0; j < 4; j++)
                    s[i][j] = fmaf(a[i], b[j], s[i][j]);
        }

        const float scale = 0.125f;
        const bool diag = (kb == qb);
        #pragma unroll
        for (int i = 0; i < 4; i++) {
            int qg = q0 + ty * 4 + i;
            #pragma unroll
            for (int j = 0; j < 4; j++) {
                s[i][j] *= scale;
                if (diag && (k0 + tx * 4 + j) > qg) s[i][j] = -1e30f;
            }
        }

        #pragma unroll
        for (int i = 0; i < 4; i++) {
            float rmax = fmaxf(fmaxf(s[i][0], s[i][1]), fmaxf(s[i][2], s[i][3]));
            #pragma unroll
            for (int off = 1; off < 16; off <<= 1)
                rmax = fmaxf(rmax, __shfl_xor_sync(0xffffffffu, rmax, off));
            float newm = fmaxf(m_i[i], rmax);
            float corr = __expf(m_i[i] - newm);
            float rsum = 0.f;
            #pragma unroll
            for (int j = 0; j < 4; j++) {
                s[i][j] = __expf(s[i][j] - newm);
                rsum += s[i][j];
            }
            #pragma unroll
            for (int off = 1; off < 16; off <<= 1)
                rsum += __shfl_xor_sync(0xffffffffu, rsum, off);
            l_i[i] = l_i[i] * corr + rsum;
            m_i[i] = newm;
            #pragma unroll
            for (int j = 0; j < 4; j++) {
                oacc[i][j] *= corr;
                PsT[(tx * 4 + j) * 64 + ty * 4 + i] = s[i][j];
            }
        }
        __syncthreads();

        #pragma unroll 8
        for (int j = 0; j < 64; j++) {
            float4 pv = *(const float4*)&PsT[j * 64 + ty * 4];
            float4 vv = *(const float4*)&Vs[j * 64 + tx * 4];
            float p[4] = {pv.x, pv.y, pv.z, pv.w};
            float v[4] = {vv.x, vv.y, vv.z, vv.w};
            #pragma unroll
            for (int i = 0; i < 4; i++)
                #pragma unroll
                for (int jj = 0; jj < 4; jj++)
                    oacc[i][jj] = fmaf(p[i], v[jj], oacc[i][jj]);
        }
    }

    #pragma unroll
    for (int i = 0; i < 4; i++) {
        float inv = 1.0f / l_i[i];
        size_t row = (size_t)(bb * SEQ + q0 + ty * 4 + i) * DMODEL + hh * HDIM;
        #pragma unroll
        for (int j = 0; j < 4; j++)
            o[row + tx * 4 + j] = oacc[i][j] * inv;
    }
}

// ---------------------------------------------------------------------------
// Host orchestration (graph-capturable: kernel launches only)
// ---------------------------------------------------------------------------
extern "C" void kernel_launch(void* const* d_in, const int* in_sizes, int n_in,
                              void* d_out, int out_size) {
    const int*   idx   = (const int*)d_in[0];
    const float* wte   = (const float*)d_in[1];
    const float* wpe   = (const float*)d_in[2];
    const float* ln1_w = (const float*)d_in[3];
    const float* ln1_b = (const float*)d_in[4];
    const float* Wqkv  = (const float*)d_in[5];
    const float* bqkv  = (const float*)d_in[6];
    const float* Wproj = (const float*)d_in[7];
    const float* bproj = (const float*)d_in[8];
    const float* ln2_w = (const float*)d_in[9];
    const float* ln2_b = (const float*)d_in[10];
    const float* Wfc   = (const float*)d_in[11];
    const float* bfc   = (const float*)d_in[12];
    const float* Wfc2  = (const float*)d_in[13];
    const float* bfc2  = (const float*)d_in[14];
    const float* lnf_w = (const float*)d_in[15];
    const float* lnf_b = (const float*)d_in[16];
    float* out = (float*)d_out;

    float *x, *h, *qkv, *o, *ff;
    cudaGetSymbolAddress((void**)&x,   g_x);
    cudaGetSymbolAddress((void**)&h,   g_h);
    cudaGetSymbolAddress((void**)&qkv, g_qkv);
    cudaGetSymbolAddress((void**)&o,   g_o);
    cudaGetSymbolAddress((void**)&ff,  g_ff);

    cudaFuncSetAttribute(attn_kernel,
                         cudaFuncAttributeMaxDynamicSharedMemorySize, 65536);

    embed_kernel<<<(NTOK * DMODEL) / 256, 256>>>(idx, wte, wpe, x);

    for (int l = 0; l < NLAYER; l++) {
        const float* wq  = Wqkv  + (size_t)l * DMODEL * 3 * DMODEL;
        const float* bq  = bqkv  + (size_t)l * 3 * DMODEL;
        const float* wp  = Wproj + (size_t)l * DMODEL * DMODEL;
        const float* bp  = bproj + (size_t)l * DMODEL;
        const float* wf1 = Wfc   + (size_t)l * DMODEL * FFDIM;
        const float* bf1 = bfc   + (size_t)l * FFDIM;
        const float* wf2 = Wfc2  + (size_t)l * FFDIM * DMODEL;
        const float* bf2 = bfc2  + (size_t)l * DMODEL;

        ln_kernel<<<NTOK, 256>>>(x, ln1_w + l * DMODEL, ln1_b + l * DMODEL, h);

        mma_gemm_kernel<false, EPI_BIAS><<<dim3(NTOK / 128, (3 * DMODEL) / 128), 256>>>(
            h, wq, bq, nullptr, qkv, NTOK, 3 * DMODEL, DMODEL);

        attn_kernel<<<dim3(SEQ / 64, NHEAD, NTOK / SEQ), 256, 65536>>>(qkv, o);

        mma_gemm_kernel<false, EPI_RES><<<dim3(NTOK / 128, DMODEL / 128), 256>>>(
            o, wp, bp, x, x, NTOK, DMODEL, DMODEL);

        ln_kernel<<<NTOK, 256>>>(x, ln2_w + l * DMODEL, ln2_b + l * DMODEL, h);

        mma_gemm_kernel<false, EPI_GELU><<<dim3(NTOK / 128, FFDIM / 128), 256>>>(
            h, wf1, bf1, nullptr, ff, NTOK, FFDIM, DMODEL);

        mma_gemm_kernel<false, EPI_RES><<<dim3(NTOK / 128, DMODEL / 128), 256>>>(
            ff, wf2, bf2, x, x, NTOK, DMODEL, FFDIM);
    }

    ln_kernel<<<NTOK, 256>>>(x, lnf_w, lnf_b, h);

    // logits = h @ wte^T  [4096, 50257] -- tf32 mma.sync
    mma_gemm_kernel<true, EPI_NONE><<<dim3(NTOK / 128, (VOCAB + 127) / 128), 256>>>(
        h, wte, nullptr, nullptr, out, NTOK, VOCAB, DMODEL);
}

// round 7
// speedup vs baseline: 2.2322x; 1.2378x over previous
#include <cuda_runtime.h>
#include <math.h>
#include <cstdint>

// ---------------------------------------------------------------------------
// GPT forward. GEMMs + attention via warp-level tf32 mma.sync (sm_80 PTX --
// compiles on plain sm_103 target; tcgen05 rejected by this harness's ptxas).
// B=2, S=2048 (4096 tokens), D=512, H=8, HD=64, FF=2048, L=4, V=50257.
// ---------------------------------------------------------------------------

#define NTOK   4096
#define DMODEL 512
#define NLAYER 4
#define NHEAD  8
#define HDIM   64
#define FFDIM  2048
#define SEQ    2048
#define VOCAB  50257

__device__ float g_x[NTOK * DMODEL];
__device__ float g_h[NTOK * DMODEL];
__device__ float g_qkv[NTOK * 3 * DMODEL];
__device__ float g_o[NTOK * DMODEL];
__device__ float g_ff[NTOK * FFDIM];

// ---------------------------------------------------------------------------
// tf32 helpers
// ---------------------------------------------------------------------------
__device__ __forceinline__ float rtf32(float x) {
    uint32_t u;
    asm("cvt.rna.tf32.f32 %0, %1;" : "=r"(u) : "f"(x));
    return __uint_as_float(u);
}

__device__ __forceinline__ float4 rtf32x4(float4 v) {
    uint32_t a, b, c, d;
    asm("cvt.rna.tf32.f32 %0, %1;" : "=r"(a) : "f"(v.x));
    asm("cvt.rna.tf32.f32 %0, %1;" : "=r"(b) : "f"(v.y));
    asm("cvt.rna.tf32.f32 %0, %1;" : "=r"(c) : "f"(v.z));
    asm("cvt.rna.tf32.f32 %0, %1;" : "=r"(d) : "f"(v.w));
    v.x = __uint_as_float(a); v.y = __uint_as_float(b);
    v.z = __uint_as_float(c); v.w = __uint_as_float(d);
    return v;
}

__device__ __forceinline__ void mma_tf32(float* d, const uint32_t* a,
                                         const uint32_t* b) {
    asm volatile(
        "mma.sync.aligned.m16n8k8.row.col.f32.tf32.tf32.f32 "
        "{%0,%1,%2,%3}, {%4,%5,%6,%7}, {%8,%9}, {%0,%1,%2,%3};"
        : "+f"(d[0]), "+f"(d[1]), "+f"(d[2]), "+f"(d[3])
        : "r"(a[0]), "r"(a[1]), "r"(a[2]), "r"(a[3]),
          "r"(b[0]), "r"(b[1]));
}

__device__ __forceinline__ void mma_tf32_b(float* d, const uint32_t* a,
                                           uint32_t b0, uint32_t b1) {
    asm volatile(
        "mma.sync.aligned.m16n8k8.row.col.f32.tf32.tf32.f32 "
        "{%0,%1,%2,%3}, {%4,%5,%6,%7}, {%8,%9}, {%0,%1,%2,%3};"
        : "+f"(d[0]), "+f"(d[1]), "+f"(d[2]), "+f"(d[3])
        : "r"(a[0]), "r"(a[1]), "r"(a[2]), "r"(a[3]),
          "r"(b0), "r"(b1));
}

// ---------------------------------------------------------------------------
// Embedding
// ---------------------------------------------------------------------------
__global__ void embed_kernel(const int* __restrict__ idx,
                             const float* __restrict__ wte,
                             const float* __restrict__ wpe,
                             float* __restrict__ x) {
    int i = blockIdx.x * 256 + threadIdx.x;
    int tok = i >> 9;
    int d   = i & 511;
    int s   = tok & (SEQ - 1);
    x[i] = wte[(size_t)idx[tok] * DMODEL + d] + wpe[s * DMODEL + d];
}

// ---------------------------------------------------------------------------
// LayerNorm over last dim (512)
// ---------------------------------------------------------------------------
__global__ void ln_kernel(const float* __restrict__ x,
                          const float* __restrict__ w,
                          const float* __restrict__ b,
                          float* __restrict__ out) {
    int row = blockIdx.x;
    int tid = threadIdx.x;
    const float* xr = x + (size_t)row * DMODEL;
    float v0 = xr[tid];
    float v1 = xr[tid + 256];
    float s  = v0 + v1;
    float sq = v0 * v0 + v1 * v1;
    #pragma unroll
    for (int off = 16; off >= 1; off >>= 1) {
        s  += __shfl_xor_sync(0xffffffffu, s,  off);
        sq += __shfl_xor_sync(0xffffffffu, sq, off);
    }
    __shared__ float ss[8], ssq[8];
    int warp = tid >> 5, lane = tid & 31;
    if (lane == 0) { ss[warp] = s; ssq[warp] = sq; }
    __syncthreads();
    float ts = 0.f, tq = 0.f;
    #pragma unroll
    for (int wI = 0; wI < 8; wI++) { ts += ss[wI]; tq += ssq[wI]; }
    float mean = ts * (1.0f / DMODEL);
    float var  = tq * (1.0f / DMODEL) - mean * mean;
    float rstd = rsqrtf(var + 1e-5f);
    float* outr = out + (size_t)row * DMODEL;
    outr[tid]       = (v0 - mean) * rstd * w[tid]       + b[tid];
    outr[tid + 256] = (v1 - mean) * rstd * w[tid + 256] + b[tid + 256];
}

// ---------------------------------------------------------------------------
// tf32 mma GEMM (passing since R4). CTA 128x128, K chunk 32.
// ---------------------------------------------------------------------------
#define EPI_BIAS 0
#define EPI_GELU 1
#define EPI_RES  2
#define EPI_NONE 3

template<bool TRANSB, int EPI>
__global__ __launch_bounds__(256)
void mma_gemm_kernel(const float* __restrict__ A, const float* __restrict__ B,
                     const float* __restrict__ bias, const float* __restrict__ R,
                     float* __restrict__ C, int M, int N, int K) {
    __shared__ float As[32][136];
    __shared__ float Bs[32][136];

    const int tid  = threadIdx.x;
    const int lane = tid & 31;
    const int wid  = tid >> 5;
    const int wm   = wid & 1;
    const int wn   = wid >> 1;
    const int m0   = blockIdx.x * 128;
    const int n0   = blockIdx.y * 128;

    const int tig  = lane & 3;
    const int grp  = lane >> 2;

    float acc[4][4][4];
    #pragma unroll
    for (int i = 0; i < 4; i++)
        #pragma unroll
        for (int j = 0; j < 4; j++)
            #pragma unroll
            for (int r = 0; r < 4; r++) acc[i][j][r] = 0.f;

    const int st_r  = tid >> 1;
    const int st_k0 = (tid & 1) * 16;
    const int bq_n  = (tid & 31) * 4;
    const int bq_k  = tid >> 5;

    const int nchunk = K >> 5;

    float4 pa[4], pb[4];

    {
        const float* Ap = A + (size_t)(m0 + st_r) * K + st_k0;
        #pragma unroll
        for (int u = 0; u < 4; u++)
            pa[u] = *(const float4*)(Ap + u * 4);
        if (!TRANSB) {
            #pragma unroll
            for (int u = 0; u < 4; u++)
                pb[u] = *(const float4*)(B + (size_t)(u * 8 + bq_k) * N + n0 + bq_n);
        } else {
            int n = n0 + st_r;
            if (n < N) {
                const float* Bp = B + (size_t)n * K + st_k0;
                #pragma unroll
                for (int u = 0; u < 4; u++)
                    pb[u] = *(const float4*)(Bp + u * 4);
            } else {
                #pragma unroll
                for (int u = 0; u < 4; u++)
                    pb[u] = make_float4(0.f, 0.f, 0.f, 0.f);
            }
        }
    }

    #pragma unroll 1
    for (int ch = 0; ch < nchunk; ch++) {
        __syncthreads();
        #pragma unroll
        for (int u = 0; u < 4; u++) {
            float4 av = rtf32x4(pa[u]);
            int k = st_k0 + u * 4;
            As[k + 0][st_r] = av.x;
            As[k + 1][st_r] = av.y;
            As[k + 2][st_r] = av.z;
            As[k + 3][st_r] = av.w;
            float4 bv = rtf32x4(pb[u]);
            if (!TRANSB) {
                *(float4*)&Bs[u * 8 + bq_k][bq_n] = bv;
            } else {
                Bs[k + 0][st_r] = bv.x;
                Bs[k + 1][st_r] = bv.y;
                Bs[k + 2][st_r] = bv.z;
                Bs[k + 3][st_r] = bv.w;
            }
        }
        __syncthreads();

        if (ch + 1 < nchunk) {
            const int k0 = (ch + 1) * 32;
            const float* Ap = A + (size_t)(m0 + st_r) * K + k0 + st_k0;
            #pragma unroll
            for (int u = 0; u < 4; u++)
                pa[u] = *(const float4*)(Ap + u * 4);
            if (!TRANSB) {
                #pragma unroll
                for (int u = 0; u < 4; u++)
                    pb[u] = *(const float4*)(B + (size_t)(k0 + u * 8 + bq_k) * N + n0 + bq_n);
            } else {
                int n = n0 + st_r;
                if (n < N) {
                    const float* Bp = B + (size_t)n * K + k0 + st_k0;
                    #pragma unroll
                    for (int u = 0; u < 4; u++)
                        pb[u] = *(const float4*)(Bp + u * 4);
                }
            }
        }

        #pragma unroll
        for (int ks = 0; ks < 4; ks++) {
            const int c = ks * 8 + tig;
            uint32_t af[4][4];
            #pragma unroll
            for (int mf = 0; mf < 4; mf++) {
                int r = wm * 64 + mf * 16 + grp;
                af[mf][0] = __float_as_uint(As[c][r]);
                af[mf][1] = __float_as_uint(As[c][r + 8]);
                af[mf][2] = __float_as_uint(As[c + 4][r]);
                af[mf][3] = __float_as_uint(As[c + 4][r + 8]);
            }
            uint32_t bf[4][2];
            #pragma unroll
            for (int nf = 0; nf < 4; nf++) {
                int n = wn * 32 + nf * 8 + grp;
                bf[nf][0] = __float_as_uint(Bs[c][n]);
                bf[nf][1] = __float_as_uint(Bs[c + 4][n]);
            }
            #pragma unroll
            for (int mf = 0; mf < 4; mf++)
                #pragma unroll
                for (int nf = 0; nf < 4; nf++)
                    mma_tf32(acc[mf][nf], af[mf], bf[nf]);
        }
    }

    #pragma unroll
    for (int mf = 0; mf < 4; mf++) {
        #pragma unroll
        for (int half = 0; half < 2; half++) {
            int row = m0 + wm * 64 + mf * 16 + grp + half * 8;
            size_t ro = (size_t)row * N;
            #pragma unroll
            for (int nf = 0; nf < 4; nf++) {
                int col = n0 + wn * 32 + nf * 8 + tig * 2;
                float v0 = acc[mf][nf][half * 2 + 0];
                float v1 = acc[mf][nf][half * 2 + 1];
                if (EPI != EPI_NONE) { v0 += bias[col]; v1 += bias[col + 1]; }
                if (EPI == EPI_GELU) {
                    v0 = 0.5f * v0 * (1.0f + erff(v0 * 0.70710678118654752f));
                    v1 = 0.5f * v1 * (1.0f + erff(v1 * 0.70710678118654752f));
                }
                if (EPI == EPI_RES) { v0 += R[ro + col]; v1 += R[ro + col + 1]; }
                if (!TRANSB) {
                    C[ro + col]     = v0;
                    C[ro + col + 1] = v1;
                } else {
                    if (col < N)     C[ro + col]     = v0;
                    if (col + 1 < N) C[ro + col + 1] = v1;
                }
            }
        }
    }
}

// ---------------------------------------------------------------------------
// Causal flash attention via tf32 mma.sync.
// CTA = (64 q-rows, head, batch); 128 threads = 4 warps x 16 q-rows.
// S = Q@K^T: single tf32. O = P@V: 3-MMA hi/lo split.
// Staging loops: 128 threads x 8 float4 = 1024 float4 = full 64x64 tile
// (R5 bug: u<4 staged only half the tile).
// ---------------------------------------------------------------------------
#define ATTN_SMEM 89088   // 22272 floats

__global__ __launch_bounds__(128)
void attn_mma_kernel(const float* __restrict__ qkv, float* __restrict__ o) {
    extern __shared__ float sm[];
    float* Ks = sm;              // [64][68]  (Q staging first, then K tiles)
    float* Vh = sm + 4352;       // [64][72]
    float* Vl = sm + 8960;       // [64][72]
    float* Ph = sm + 13568;      // [64][68]
    float* Pl = sm + 17920;      // [64][68]

    const int tid  = threadIdx.x;
    const int lane = tid & 31;
    const int warp = tid >> 5;
    const int grp  = lane >> 2;
    const int tig  = lane & 3;
    const int qb = blockIdx.x, hh = blockIdx.y, bb = blockIdx.z;
    const int q0 = qb * 64;
    const size_t tokbase = (size_t)bb * SEQ;

    // ---- stage Q tile (full 64x64: 8 x 128 threads x float4) ----
    #pragma unroll
    for (int u = 0; u < 8; u++) {
        int idx = u * 128 + tid;          // 0..1023
        int r = idx >> 4;                 // row 0..63
        int c = (idx & 15) << 2;          // col 0..60
        const float* src = qkv + (tokbase + q0 + r) * 1536 + hh * 64 + c;
        *(float4*)&Ks[r * 68 + c] = *(const float4*)src;
    }
    __syncthreads();

    uint32_t qa[8][4];
    {
        const int r0 = (warp * 16 + grp) * 68;
        const int r1 = r0 + 8 * 68;
        #pragma unroll
        for (int kf = 0; kf < 8; kf++) {
            int c = kf * 8 + tig;
            qa[kf][0] = __float_as_uint(rtf32(Ks[r0 + c]));
            qa[kf][1] = __float_as_uint(rtf32(Ks[r1 + c]));
            qa[kf][2] = __float_as_uint(rtf32(Ks[r0 + c + 4]));
            qa[kf][3] = __float_as_uint(rtf32(Ks[r1 + c + 4]));
        }
    }

    float m0 = -1e30f, m1 = -1e30f, l0 = 0.f, l1 = 0.f;
    float oacc[8][4];
    #pragma unroll
    for (int nf = 0; nf < 8; nf++)
        #pragma unroll
        for (int c = 0; c < 4; c++) oacc[nf][c] = 0.f;

    const int prow0 = (warp * 16 + grp) * 68;
    const int prow1 = prow0 + 8 * 68;
    const int row0g = q0 + warp * 16 + grp;
    const int row1g = row0g + 8;

    #pragma unroll 1
    for (int kb = 0; kb <= qb; kb++) {
        const int k0 = kb * 64;
        __syncthreads();   // prior tile's Ks/Vh/Vl reads complete
        // ---- stage K (tf32-rounded) and V (hi/lo split), full tiles ----
        #pragma unroll
        for (int u = 0; u < 8; u++) {
            int idx = u * 128 + tid;
            int r = idx >> 4;
            int c = (idx & 15) << 2;
            const float* kp = qkv + (tokbase + k0 + r) * 1536 + 512 + hh * 64 + c;
            *(float4*)&Ks[r * 68 + c] = rtf32x4(*(const float4*)kp);
            const float* vp = qkv + (tokbase + k0 + r) * 1536 + 1024 + hh * 64 + c;
            float4 v  = *(const float4*)vp;
            float4 vh = rtf32x4(v);
            float4 vl;
            vl.x = v.x - vh.x; vl.y = v.y - vh.y;
            vl.z = v.z - vh.z; vl.w = v.w - vh.w;
            vl = rtf32x4(vl);
            *(float4*)&Vh[r * 72 + c] = vh;
            *(float4*)&Vl[r * 72 + c] = vl;
        }
        __syncthreads();

        // ---- S = Q @ K^T ----
        float sacc[8][4];
        #pragma unroll
        for (int nf = 0; nf < 8; nf++) {
            #pragma unroll
            for (int c = 0; c < 4; c++) sacc[nf][c] = 0.f;
            const int kb_row = (nf * 8 + grp) * 68;
            #pragma unroll
            for (int kf = 0; kf < 8; kf++) {
                uint32_t b0 = __float_as_uint(Ks[kb_row + kf * 8 + tig]);
                uint32_t b1 = __float_as_uint(Ks[kb_row + kf * 8 + tig + 4]);
                mma_tf32_b(sacc[nf], qa[kf], b0, b1);
            }
        }

        // ---- scale + causal mask ----
        const float scale = 0.125f;
        #pragma unroll
        for (int nf = 0; nf < 8; nf++) {
            int colb = k0 + nf * 8 + 2 * tig;
            sacc[nf][0] = (colb     > row0g) ? -1e30f : sacc[nf][0] * scale;
            sacc[nf][1] = (colb + 1 > row0g) ? -1e30f : sacc[nf][1] * scale;
            sacc[nf][2] = (colb     > row1g) ? -1e30f : sacc[nf][2] * scale;
            sacc[nf][3] = (colb + 1 > row1g) ? -1e30f : sacc[nf][3] * scale;
        }

        // ---- online softmax (rows owned by tig-quads) ----
        float rm0 = -1e30f, rm1 = -1e30f;
        #pragma unroll
        for (int nf = 0; nf < 8; nf++) {
            rm0 = fmaxf(rm0, fmaxf(sacc[nf][0], sacc[nf][1]));
            rm1 = fmaxf(rm1, fmaxf(sacc[nf][2], sacc[nf][3]));
        }
        rm0 = fmaxf(rm0, __shfl_xor_sync(0xffffffffu, rm0, 1));
        rm0 = fmaxf(rm0, __shfl_xor_sync(0xffffffffu, rm0, 2));
        rm1 = fmaxf(rm1, __shfl_xor_sync(0xffffffffu, rm1, 1));
        rm1 = fmaxf(rm1, __shfl_xor_sync(0xffffffffu, rm1, 2));
        float nm0 = fmaxf(m0, rm0), nm1 = fmaxf(m1, rm1);
        float corr0 = __expf(m0 - nm0), corr1 = __expf(m1 - nm1);
        float rs0 = 0.f, rs1 = 0.f;
        #pragma unroll
        for (int nf = 0; nf < 8; nf++) {
            float p0 = __expf(sacc[nf][0] - nm0);
            float p1 = __expf(sacc[nf][1] - nm0);
            float p2 = __expf(sacc[nf][2] - nm1);
            float p3 = __expf(sacc[nf][3] - nm1);
            rs0 += p0 + p1; rs1 += p2 + p3;
            sacc[nf][0] = p0; sacc[nf][1] = p1;
            sacc[nf][2] = p2; sacc[nf][3] = p3;
        }
        rs0 += __shfl_xor_sync(0xffffffffu, rs0, 1);
        rs0 += __shfl_xor_sync(0xffffffffu, rs0, 2);
        rs1 += __shfl_xor_sync(0xffffffffu, rs1, 1);
        rs1 += __shfl_xor_sync(0xffffffffu, rs1, 2);
        l0 = l0 * corr0 + rs0;  m0 = nm0;
        l1 = l1 * corr1 + rs1;  m1 = nm1;
        #pragma unroll
        for (int nf = 0; nf < 8; nf++) {
            oacc[nf][0] *= corr0; oacc[nf][1] *= corr0;
            oacc[nf][2] *= corr1; oacc[nf][3] *= corr1;
        }

        // ---- P hi/lo to warp-private smem strip ----
        #pragma unroll
        for (int nf = 0; nf < 8; nf++) {
            int cc = nf * 8 + 2 * tig;
            float ph, pl;
            ph = rtf32(sacc[nf][0]); pl = rtf32(sacc[nf][0] - ph);
            Ph[prow0 + cc] = ph; Pl[prow0 + cc] = pl;
            ph = rtf32(sacc[nf][1]); pl = rtf32(sacc[nf][1] - ph);
            Ph[prow0 + cc + 1] = ph; Pl[prow0 + cc + 1] = pl;
            ph = rtf32(sacc[nf][2]); pl = rtf32(sacc[nf][2] - ph);
            Ph[prow1 + cc] = ph; Pl[prow1 + cc] = pl;
            ph = rtf32(sacc[nf][3]); pl = rtf32(sacc[nf][3] - ph);
            Ph[prow1 + cc + 1] = ph; Pl[prow1 + cc + 1] = pl;
        }
        __syncwarp();

        // ---- O += P @ V  (3-term split) ----
        #pragma unroll
        for (int kf = 0; kf < 8; kf++) {
            uint32_t ah[4], al[4];
            int c = kf * 8 + tig;
            ah[0] = __float_as_uint(Ph[prow0 + c]);
            ah[1] = __float_as_uint(Ph[prow1 + c]);
            ah[2] = __float_as_uint(Ph[prow0 + c + 4]);
            ah[3] = __float_as_uint(Ph[prow1 + c + 4]);
            al[0] = __float_as_uint(Pl[prow0 + c]);
            al[1] = __float_as_uint(Pl[prow1 + c]);
            al[2] = __float_as_uint(Pl[prow0 + c + 4]);
            al[3] = __float_as_uint(Pl[prow1 + c + 4]);
            const int vr0 = (kf * 8 + tig) * 72;
            const int vr1 = (kf * 8 + tig + 4) * 72;
            #pragma unroll
            for (int nf = 0; nf < 8; nf++) {
                int n = nf * 8 + grp;
                uint32_t b0h = __float_as_uint(Vh[vr0 + n]);
                uint32_t b1h = __float_as_uint(Vh[vr1 + n]);
                uint32_t b0l = __float_as_uint(Vl[vr0 + n]);
                uint32_t b1l = __float_as_uint(Vl[vr1 + n]);
                mma_tf32_b(oacc[nf], ah, b0h, b1h);
                mma_tf32_b(oacc[nf], ah, b0l, b1l);
                mma_tf32_b(oacc[nf], al, b0h, b1h);
            }
        }
    }

    // ---- finalize + store ----
    const float inv0 = 1.0f / l0, inv1 = 1.0f / l1;
    const size_t ob0 = (tokbase + row0g) * DMODEL + hh * 64;
    const size_t ob1 = (tokbase + row1g) * DMODEL + hh * 64;
    #pragma unroll
    for (int nf = 0; nf < 8; nf++) {
        int cc = nf * 8 + 2 * tig;
        o[ob0 + cc]     = oacc[nf][0] * inv0;
        o[ob0 + cc + 1] = oacc[nf][1] * inv0;
        o[ob1 + cc]     = oacc[nf][2] * inv1;
        o[ob1 + cc + 1] = oacc[nf][3] * inv1;
    }
}

// ---------------------------------------------------------------------------
// Host orchestration (graph-capturable: kernel launches only)
// ---------------------------------------------------------------------------
extern "C" void kernel_launch(void* const* d_in, const int* in_sizes, int n_in,
                              void* d_out, int out_size) {
    const int*   idx   = (const int*)d_in[0];
    const float* wte   = (const float*)d_in[1];
    const float* wpe   = (const float*)d_in[2];
    const float* ln1_w = (const float*)d_in[3];
    const float* ln1_b = (const float*)d_in[4];
    const float* Wqkv  = (const float*)d_in[5];
    const float* bqkv  = (const float*)d_in[6];
    const float* Wproj = (const float*)d_in[7];
    const float* bproj = (const float*)d_in[8];
    const float* ln2_w = (const float*)d_in[9];
    const float* ln2_b = (const float*)d_in[10];
    const float* Wfc   = (const float*)d_in[11];
    const float* bfc   = (const float*)d_in[12];
    const float* Wfc2  = (const float*)d_in[13];
    const float* bfc2  = (const float*)d_in[14];
    const float* lnf_w = (const float*)d_in[15];
    const float* lnf_b = (const float*)d_in[16];
    float* out = (float*)d_out;

    float *x, *h, *qkv, *o, *ff;
    cudaGetSymbolAddress((void**)&x,   g_x);
    cudaGetSymbolAddress((void**)&h,   g_h);
    cudaGetSymbolAddress((void**)&qkv, g_qkv);
    cudaGetSymbolAddress((void**)&o,   g_o);
    cudaGetSymbolAddress((void**)&ff,  g_ff);

    cudaFuncSetAttribute(attn_mma_kernel,
                         cudaFuncAttributeMaxDynamicSharedMemorySize, ATTN_SMEM);

    embed_kernel<<<(NTOK * DMODEL) / 256, 256>>>(idx, wte, wpe, x);

    for (int l = 0; l < NLAYER; l++) {
        const float* wq  = Wqkv  + (size_t)l * DMODEL * 3 * DMODEL;
        const float* bq  = bqkv  + (size_t)l * 3 * DMODEL;
        const float* wp  = Wproj + (size_t)l * DMODEL * DMODEL;
        const float* bp  = bproj + (size_t)l * DMODEL;
        const float* wf1 = Wfc   + (size_t)l * DMODEL * FFDIM;
        const float* bf1 = bfc   + (size_t)l * FFDIM;
        const float* wf2 = Wfc2  + (size_t)l * FFDIM * DMODEL;
        const float* bf2 = bfc2  + (size_t)l * DMODEL;

        ln_kernel<<<NTOK, 256>>>(x, ln1_w + l * DMODEL, ln1_b + l * DMODEL, h);

        mma_gemm_kernel<false, EPI_BIAS><<<dim3(NTOK / 128, (3 * DMODEL) / 128), 256>>>(
            h, wq, bq, nullptr, qkv, NTOK, 3 * DMODEL, DMODEL);

        attn_mma_kernel<<<dim3(SEQ / 64, NHEAD, NTOK / SEQ), 128, ATTN_SMEM>>>(qkv, o);

        mma_gemm_kernel<false, EPI_RES><<<dim3(NTOK / 128, DMODEL / 128), 256>>>(
            o, wp, bp, x, x, NTOK, DMODEL, DMODEL);

        ln_kernel<<<NTOK, 256>>>(x, ln2_w + l * DMODEL, ln2_b + l * DMODEL, h);

        mma_gemm_kernel<false, EPI_GELU><<<dim3(NTOK / 128, FFDIM / 128), 256>>>(
            h, wf1, bf1, nullptr, ff, NTOK, FFDIM, DMODEL);

        mma_gemm_kernel<false, EPI_RES><<<dim3(NTOK / 128, DMODEL / 128), 256>>>(
            ff, wf2, bf2, x, x, NTOK, DMODEL, FFDIM);
    }

    ln_kernel<<<NTOK, 256>>>(x, lnf_w, lnf_b, h);

    mma_gemm_kernel<true, EPI_NONE><<<dim3(NTOK / 128, (VOCAB + 127) / 128), 256>>>(
        h, wte, nullptr, nullptr, out, NTOK, VOCAB, DMODEL);
}

// round 8
// speedup vs baseline: 2.5830x; 1.1572x over previous
#include <cuda_runtime.h>
#include <math.h>
#include <cstdint>

// ---------------------------------------------------------------------------
// GPT forward. GEMMs + attention via warp-level tf32 mma.sync (sm_80 PTX --
// compiles on plain sm_103 target; tcgen05 rejected by this harness's ptxas).
// Big GEMMs (QKV/FC1/lm_head): 128x256 CTA tile, 64x64 warp tile, cp.async
// double-buffered. Small-N GEMMs (proj/FC2): 128x128 narrow kernel.
// B=2, S=2048 (4096 tokens), D=512, H=8, HD=64, FF=2048, L=4, V=50257.
// ---------------------------------------------------------------------------

#define NTOK   4096
#define DMODEL 512
#define NLAYER 4
#define NHEAD  8
#define HDIM   64
#define FFDIM  2048
#define SEQ    2048
#define VOCAB  50257

__device__ float g_x[NTOK * DMODEL];
__device__ float g_h[NTOK * DMODEL];
__device__ float g_qkv[NTOK * 3 * DMODEL];
__device__ float g_o[NTOK * DMODEL];
__device__ float g_ff[NTOK * FFDIM];

// ---------------------------------------------------------------------------
// tf32 / cp.async helpers
// ---------------------------------------------------------------------------
__device__ __forceinline__ float rtf32(float x) {
    uint32_t u;
    asm("cvt.rna.tf32.f32 %0, %1;" : "=r"(u) : "f"(x));
    return __uint_as_float(u);
}

__device__ __forceinline__ uint32_t ldtf(const float* s) {
    uint32_t u;
    asm("cvt.rna.tf32.f32 %0, %1;" : "=r"(u) : "f"(*s));
    return u;
}

__device__ __forceinline__ float4 rtf32x4(float4 v) {
    uint32_t a, b, c, d;
    asm("cvt.rna.tf32.f32 %0, %1;" : "=r"(a) : "f"(v.x));
    asm("cvt.rna.tf32.f32 %0, %1;" : "=r"(b) : "f"(v.y));
    asm("cvt.rna.tf32.f32 %0, %1;" : "=r"(c) : "f"(v.z));
    asm("cvt.rna.tf32.f32 %0, %1;" : "=r"(d) : "f"(v.w));
    v.x = __uint_as_float(a); v.y = __uint_as_float(b);
    v.z = __uint_as_float(c); v.w = __uint_as_float(d);
    return v;
}

__device__ __forceinline__ void mma_tf32(float* d, const uint32_t* a,
                                         const uint32_t* b) {
    asm volatile(
        "mma.sync.aligned.m16n8k8.row.col.f32.tf32.tf32.f32 "
        "{%0,%1,%2,%3}, {%4,%5,%6,%7}, {%8,%9}, {%0,%1,%2,%3};"
        : "+f"(d[0]), "+f"(d[1]), "+f"(d[2]), "+f"(d[3])
        : "r"(a[0]), "r"(a[1]), "r"(a[2]), "r"(a[3]),
          "r"(b[0]), "r"(b[1]));
}

__device__ __forceinline__ void mma_tf32_b(float* d, const uint32_t* a,
                                           uint32_t b0, uint32_t b1) {
    asm volatile(
        "mma.sync.aligned.m16n8k8.row.col.f32.tf32.tf32.f32 "
        "{%0,%1,%2,%3}, {%4,%5,%6,%7}, {%8,%9}, {%0,%1,%2,%3};"
        : "+f"(d[0]), "+f"(d[1]), "+f"(d[2]), "+f"(d[3])
        : "r"(a[0]), "r"(a[1]), "r"(a[2]), "r"(a[3]),
          "r"(b0), "r"(b1));
}

__device__ __forceinline__ uint32_t cvsm(const void* p) {
    return (uint32_t)__cvta_generic_to_shared(p);
}
#define CP_A16(dst, src) \
    asm volatile("cp.async.ca.shared.global [%0], [%1], 16;" \
                 :: "r"(dst), "l"(src))
#define CP_A16Z(dst, src, sb) \
    asm volatile("cp.async.ca.shared.global [%0], [%1], 16, %2;" \
                 :: "r"(dst), "l"(src), "r"(sb))
#define CP_COMMIT() asm volatile("cp.async.commit_group;")
#define CP_WAIT(n)  asm volatile("cp.async.wait_group %0;" :: "n"(n))

// ---------------------------------------------------------------------------
// Embedding
// ---------------------------------------------------------------------------
__global__ void embed_kernel(const int* __restrict__ idx,
                             const float* __restrict__ wte,
                             const float* __restrict__ wpe,
                             float* __restrict__ x) {
    int i = blockIdx.x * 256 + threadIdx.x;
    int tok = i >> 9;
    int d   = i & 511;
    int s   = tok & (SEQ - 1);
    x[i] = wte[(size_t)idx[tok] * DMODEL + d] + wpe[s * DMODEL + d];
}

// ---------------------------------------------------------------------------
// LayerNorm over last dim (512)
// ---------------------------------------------------------------------------
__global__ void ln_kernel(const float* __restrict__ x,
                          const float* __restrict__ w,
                          const float* __restrict__ b,
                          float* __restrict__ out) {
    int row = blockIdx.x;
    int tid = threadIdx.x;
    const float* xr = x + (size_t)row * DMODEL;
    float v0 = xr[tid];
    float v1 = xr[tid + 256];
    float s  = v0 + v1;
    float sq = v0 * v0 + v1 * v1;
    #pragma unroll
    for (int off = 16; off >= 1; off >>= 1) {
        s  += __shfl_xor_sync(0xffffffffu, s,  off);
        sq += __shfl_xor_sync(0xffffffffu, sq, off);
    }
    __shared__ float ss[8], ssq[8];
    int warp = tid >> 5, lane = tid & 31;
    if (lane == 0) { ss[warp] = s; ssq[warp] = sq; }
    __syncthreads();
    float ts = 0.f, tq = 0.f;
    #pragma unroll
    for (int wI = 0; wI < 8; wI++) { ts += ss[wI]; tq += ssq[wI]; }
    float mean = ts * (1.0f / DMODEL);
    float var  = tq * (1.0f / DMODEL) - mean * mean;
    float rstd = rsqrtf(var + 1e-5f);
    float* outr = out + (size_t)row * DMODEL;
    outr[tid]       = (v0 - mean) * rstd * w[tid]       + b[tid];
    outr[tid + 256] = (v1 - mean) * rstd * w[tid + 256] + b[tid + 256];
}

#define EPI_BIAS 0
#define EPI_GELU 1
#define EPI_RES  2
#define EPI_NONE 3

// ---------------------------------------------------------------------------
// WIDE tf32 GEMM: CTA 128x256, 8 warps (2m x 4n) at 64x64 each, K chunk 32,
// cp.async double-buffered staging, cvt.rna at fragment load.
//   TRANSB=false: B [K,N] row-major, N % 256 == 0.  (QKV, FC1)
//   TRANSB=true : B [N,K] row-major, N guarded.     (lm_head)
// Smem: A 2x[128][36], B 2x[256][36]-capacity  => 110592 bytes dynamic.
// All fragment LDS patterns verified conflict-free (32 distinct banks).
// ---------------------------------------------------------------------------
#define WGEMM_SMEM 110592

template<bool TRANSB, int EPI>
__global__ __launch_bounds__(256)
void wgemm_kernel(const float* __restrict__ A, const float* __restrict__ B,
                  const float* __restrict__ bias, const float* __restrict__ R,
                  float* __restrict__ C, int M, int N, int K) {
    extern __shared__ float wsm[];
    float* const As0 = wsm;
    float* const As1 = wsm + 4608;
    float* const Bs0 = wsm + 9216;
    float* const Bs1 = wsm + 18432;

    const int tid  = threadIdx.x;
    const int lane = tid & 31;
    const int warp = tid >> 5;
    const int wm   = warp & 1;
    const int wn   = warp >> 1;         // 0..3
    const int grp  = lane >> 2;
    const int tig  = lane & 3;
    const int m0   = blockIdx.x * 128;
    const int n0   = blockIdx.y * 256;

    float acc[4][8][4];
    #pragma unroll
    for (int i = 0; i < 4; i++)
        #pragma unroll
        for (int j = 0; j < 8; j++)
            #pragma unroll
            for (int r = 0; r < 4; r++) acc[i][j][r] = 0.f;

    const int nchunk = K >> 5;

    auto stage = [&](int ch, float* As, float* Bs) {
        // A tile: 128 rows x 32 k-floats -> [row][36]
        {
            const int row = tid >> 1;
            const int f4b = (tid & 1) * 4;           // float4 index 0 or 4
            const float* g = A + (size_t)(m0 + row) * K + ch * 32 + f4b * 4;
            uint32_t s = cvsm(&As[row * 36 + f4b * 4]);
            #pragma unroll
            for (int u = 0; u < 4; u++)
                CP_A16(s + u * 16, g + u * 4);
        }
        if (!TRANSB) {
            // B tile: 32 k-rows x 256 n-floats -> [k][264]
            const int n4  = tid & 31;
            const int kr0 = tid >> 5;
            #pragma unroll
            for (int u = 0; u < 4; u++) {
                int kr = kr0 + u * 8;
                const float* g = B + (size_t)(ch * 32 + kr) * N + n0 + n4 * 4;
                uint32_t s = cvsm(&Bs[kr * 264 + n4 * 4]);
                CP_A16(s, g);
                CP_A16(s + 512, g + 128);            // +128 floats
            }
        } else {
            // B tile: 256 n-rows x 32 k-floats -> [n][36], OOB rows zero-filled
            #pragma unroll
            for (int h = 0; h < 2; h++) {
                int nr = (tid >> 1) + h * 128;
                int gn = n0 + nr;
                uint32_t sb  = (gn < N) ? 16u : 0u;
                int      gnc = (gn < N) ? gn : 0;
                const int f4b = (tid & 1) * 4;
                const float* g = B + (size_t)gnc * K + ch * 32 + f4b * 4;
                uint32_t s = cvsm(&Bs[nr * 36 + f4b * 4]);
                #pragma unroll
                for (int u = 0; u < 4; u++)
                    CP_A16Z(s + u * 16, g + u * 4, sb);
            }
        }
    };

    stage(0, As0, Bs0);
    CP_COMMIT();

    #pragma unroll 1
    for (int ch = 0; ch < nchunk; ch++) {
        const int b = ch & 1;
        float* As = b ? As1 : As0;
        float* Bs = b ? Bs1 : Bs0;
        __syncthreads();   // compute on the other buffer fully drained
        if (ch + 1 < nchunk) {
            stage(ch + 1, b ? As0 : As1, b ? Bs0 : Bs1);
            CP_COMMIT();
            CP_WAIT(1);    // chunk ch resident
        } else {
            CP_WAIT(0);
        }
        __syncthreads();

        #pragma unroll
        for (int ks = 0; ks < 4; ks++) {
            const int c = ks * 8 + tig;
            uint32_t af[4][4];
            #pragma unroll
            for (int mf = 0; mf < 4; mf++) {
                int r = wm * 64 + mf * 16 + grp;
                af[mf][0] = ldtf(&As[r * 36 + c]);
                af[mf][1] = ldtf(&As[(r + 8) * 36 + c]);
                af[mf][2] = ldtf(&As[r * 36 + c + 4]);
                af[mf][3] = ldtf(&As[(r + 8) * 36 + c + 4]);
            }
            uint32_t bf[8][2];
            #pragma unroll
            for (int nf = 0; nf < 8; nf++) {
                int n = wn * 64 + nf * 8 + grp;
                if (!TRANSB) {
                    bf[nf][0] = ldtf(&Bs[c * 264 + n]);
                    bf[nf][1] = ldtf(&Bs[(c + 4) * 264 + n]);
                } else {
                    bf[nf][0] = ldtf(&Bs[n * 36 + c]);
                    bf[nf][1] = ldtf(&Bs[n * 36 + c + 4]);
                }
            }
            #pragma unroll
            for (int mf = 0; mf < 4; mf++)
                #pragma unroll
                for (int nf = 0; nf < 8; nf++)
                    mma_tf32(acc[mf][nf], af[mf], bf[nf]);
        }
    }

    // epilogue
    #pragma unroll
    for (int mf = 0; mf < 4; mf++) {
        #pragma unroll
        for (int half = 0; half < 2; half++) {
            int row = m0 + wm * 64 + mf * 16 + grp + half * 8;
            size_t ro = (size_t)row * N;
            #pragma unroll
            for (int nf = 0; nf < 8; nf++) {
                int col = n0 + wn * 64 + nf * 8 + tig * 2;
                float v0 = acc[mf][nf][half * 2 + 0];
                float v1 = acc[mf][nf][half * 2 + 1];
                if (EPI != EPI_NONE) { v0 += bias[col]; v1 += bias[col + 1]; }
                if (EPI == EPI_GELU) {
                    v0 = 0.5f * v0 * (1.0f + erff(v0 * 0.70710678118654752f));
                    v1 = 0.5f * v1 * (1.0f + erff(v1 * 0.70710678118654752f));
                }
                if (EPI == EPI_RES) { v0 += R[ro + col]; v1 += R[ro + col + 1]; }
                if (!TRANSB) {
                    C[ro + col]     = v0;
                    C[ro + col + 1] = v1;
                } else {
                    if (col < N)     C[ro + col]     = v0;
                    if (col + 1 < N) C[ro + col + 1] = v1;
                }
            }
        }
    }
}

// ---------------------------------------------------------------------------
// NARROW tf32 GEMM (passing since R4): CTA 128x128, used for N=512 GEMMs.
// ---------------------------------------------------------------------------
template<int EPI>
__global__ __launch_bounds__(256)
void mma_gemm_kernel(const float* __restrict__ A, const float* __restrict__ B,
                     const float* __restrict__ bias, const float* __restrict__ R,
                     float* __restrict__ C, int M, int N, int K) {
    __shared__ float As[32][136];
    __shared__ float Bs[32][136];

    const int tid  = threadIdx.x;
    const int lane = tid & 31;
    const int wid  = tid >> 5;
    const int wm   = wid & 1;
    const int wn   = wid >> 1;
    const int m0   = blockIdx.x * 128;
    const int n0   = blockIdx.y * 128;

    const int tig  = lane & 3;
    const int grp  = lane >> 2;

    float acc[4][4][4];
    #pragma unroll
    for (int i = 0; i < 4; i++)
        #pragma unroll
        for (int j = 0; j < 4; j++)
            #pragma unroll
            for (int r = 0; r < 4; r++) acc[i][j][r] = 0.f;

    const int st_r  = tid >> 1;
    const int st_k0 = (tid & 1) * 16;
    const int bq_n  = (tid & 31) * 4;
    const int bq_k  = tid >> 5;

    const int nchunk = K >> 5;

    float4 pa[4], pb[4];

    {
        const float* Ap = A + (size_t)(m0 + st_r) * K + st_k0;
        #pragma unroll
        for (int u = 0; u < 4; u++)
            pa[u] = *(const float4*)(Ap + u * 4);
        #pragma unroll
        for (int u = 0; u < 4; u++)
            pb[u] = *(const float4*)(B + (size_t)(u * 8 + bq_k) * N + n0 + bq_n);
    }

    #pragma unroll 1
    for (int ch = 0; ch < nchunk; ch++) {
        __syncthreads();
        #pragma unroll
        for (int u = 0; u < 4; u++) {
            float4 av = rtf32x4(pa[u]);
            int k = st_k0 + u * 4;
            As[k + 0][st_r] = av.x;
            As[k + 1][st_r] = av.y;
            As[k + 2][st_r] = av.z;
            As[k + 3][st_r] = av.w;
            float4 bv = rtf32x4(pb[u]);
            *(float4*)&Bs[u * 8 + bq_k][bq_n] = bv;
        }
        __syncthreads();

        if (ch + 1 < nchunk) {
            const int k0 = (ch + 1) * 32;
            const float* Ap = A + (size_t)(m0 + st_r) * K + k0 + st_k0;
            #pragma unroll
            for (int u = 0; u < 4; u++)
                pa[u] = *(const float4*)(Ap + u * 4);
            #pragma unroll
            for (int u = 0; u < 4; u++)
                pb[u] = *(const float4*)(B + (size_t)(k0 + u * 8 + bq_k) * N + n0 + bq_n);
        }

        #pragma unroll
        for (int ks = 0; ks < 4; ks++) {
            const int c = ks * 8 + tig;
            uint32_t af[4][4];
            #pragma unroll
            for (int mf = 0; mf < 4; mf++) {
                int r = wm * 64 + mf * 16 + grp;
                af[mf][0] = __float_as_uint(As[c][r]);
                af[mf][1] = __float_as_uint(As[c][r + 8]);
                af[mf][2] = __float_as_uint(As[c + 4][r]);
                af[mf][3] = __float_as_uint(As[c + 4][r + 8]);
            }
            uint32_t bf[4][2];
            #pragma unroll
            for (int nf = 0; nf < 4; nf++) {
                int n = wn * 32 + nf * 8 + grp;
                bf[nf][0] = __float_as_uint(Bs[c][n]);
                bf[nf][1] = __float_as_uint(Bs[c + 4][n]);
            }
            #pragma unroll
            for (int mf = 0; mf < 4; mf++)
                #pragma unroll
                for (int nf = 0; nf < 4; nf++)
                    mma_tf32(acc[mf][nf], af[mf], bf[nf]);
        }
    }

    #pragma unroll
    for (int mf = 0; mf < 4; mf++) {
        #pragma unroll
        for (int half = 0; half < 2; half++) {
            int row = m0 + wm * 64 + mf * 16 + grp + half * 8;
            size_t ro = (size_t)row * N;
            #pragma unroll
            for (int nf = 0; nf < 4; nf++) {
                int col = n0 + wn * 32 + nf * 8 + tig * 2;
                float v0 = acc[mf][nf][half * 2 + 0];
                float v1 = acc[mf][nf][half * 2 + 1];
                v0 += bias[col]; v1 += bias[col + 1];
                if (EPI == EPI_GELU) {
                    v0 = 0.5f * v0 * (1.0f + erff(v0 * 0.70710678118654752f));
                    v1 = 0.5f * v1 * (1.0f + erff(v1 * 0.70710678118654752f));
                }
                if (EPI == EPI_RES) { v0 += R[ro + col]; v1 += R[ro + col + 1]; }
                C[ro + col]     = v0;
                C[ro + col + 1] = v1;
            }
        }
    }
}

// ---------------------------------------------------------------------------
// Causal flash attention via tf32 mma.sync (passing R6).
// ---------------------------------------------------------------------------
#define ATTN_SMEM 89088   // 22272 floats

__global__ __launch_bounds__(128)
void attn_mma_kernel(const float* __restrict__ qkv, float* __restrict__ o) {
    extern __shared__ float sm[];
    float* Ks = sm;              // [64][68]  (Q staging first, then K tiles)
    float* Vh = sm + 4352;       // [64][72]
    float* Vl = sm + 8960;       // [64][72]
    float* Ph = sm + 13568;      // [64][68]
    float* Pl = sm + 17920;      // [64][68]

    const int tid  = threadIdx.x;
    const int lane = tid & 31;
    const int warp = tid >> 5;
    const int grp  = lane >> 2;
    const int tig  = lane & 3;
    const int qb = blockIdx.x, hh = blockIdx.y, bb = blockIdx.z;
    const int q0 = qb * 64;
    const size_t tokbase = (size_t)bb * SEQ;

    #pragma unroll
    for (int u = 0; u < 8; u++) {
        int idx = u * 128 + tid;
        int r = idx >> 4;
        int c = (idx & 15) << 2;
        const float* src = qkv + (tokbase + q0 + r) * 1536 + hh * 64 + c;
        *(float4*)&Ks[r * 68 + c] = *(const float4*)src;
    }
    __syncthreads();

    uint32_t qa[8][4];
    {
        const int r0 = (warp * 16 + grp) * 68;
        const int r1 = r0 + 8 * 68;
        #pragma unroll
        for (int kf = 0; kf < 8; kf++) {
            int c = kf * 8 + tig;
            qa[kf][0] = __float_as_uint(rtf32(Ks[r0 + c]));
            qa[kf][1] = __float_as_uint(rtf32(Ks[r1 + c]));
            qa[kf][2] = __float_as_uint(rtf32(Ks[r0 + c + 4]));
            qa[kf][3] = __float_as_uint(rtf32(Ks[r1 + c + 4]));
        }
    }

    float m0 = -1e30f, m1 = -1e30f, l0 = 0.f, l1 = 0.f;
    float oacc[8][4];
    #pragma unroll
    for (int nf = 0; nf < 8; nf++)
        #pragma unroll
        for (int c = 0; c < 4; c++) oacc[nf][c] = 0.f;

    const int prow0 = (warp * 16 + grp) * 68;
    const int prow1 = prow0 + 8 * 68;
    const int row0g = q0 + warp * 16 + grp;
    const int row1g = row0g + 8;

    #pragma unroll 1
    for (int kb = 0; kb <= qb; kb++) {
        const int k0 = kb * 64;
        __syncthreads();
        #pragma unroll
        for (int u = 0; u < 8; u++) {
            int idx = u * 128 + tid;
            int r = idx >> 4;
            int c = (idx & 15) << 2;
            const float* kp = qkv + (tokbase + k0 + r) * 1536 + 512 + hh * 64 + c;
            *(float4*)&Ks[r * 68 + c] = rtf32x4(*(const float4*)kp);
            const float* vp = qkv + (tokbase + k0 + r) * 1536 + 1024 + hh * 64 + c;
            float4 v  = *(const float4*)vp;
            float4 vh = rtf32x4(v);
            float4 vl;
            vl.x = v.x - vh.x; vl.y = v.y - vh.y;
            vl.z = v.z - vh.z; vl.w = v.w - vh.w;
            vl = rtf32x4(vl);
            *(float4*)&Vh[r * 72 + c] = vh;
            *(float4*)&Vl[r * 72 + c] = vl;
        }
        __syncthreads();

        float sacc[8][4];
        #pragma unroll
        for (int nf = 0; nf < 8; nf++) {
            #pragma unroll
            for (int c = 0; c < 4; c++) sacc[nf][c] = 0.f;
            const int kb_row = (nf * 8 + grp) * 68;
            #pragma unroll
            for (int kf = 0; kf < 8; kf++) {
                uint32_t b0 = __float_as_uint(Ks[kb_row + kf * 8 + tig]);
                uint32_t b1 = __float_as_uint(Ks[kb_row + kf * 8 + tig + 4]);
                mma_tf32_b(sacc[nf], qa[kf], b0, b1);
            }
        }

        const float scale = 0.125f;
        #pragma unroll
        for (int nf = 0; nf < 8; nf++) {
            int colb = k0 + nf * 8 + 2 * tig;
            sacc[nf][0] = (colb     > row0g) ? -1e30f : sacc[nf][0] * scale;
            sacc[nf][1] = (colb + 1 > row0g) ? -1e30f : sacc[nf][1] * scale;
            sacc[nf][2] = (colb     > row1g) ? -1e30f : sacc[nf][2] * scale;
            sacc[nf][3] = (colb + 1 > row1g) ? -1e30f : sacc[nf][3] * scale;
        }

        float rm0 = -1e30f, rm1 = -1e30f;
        #pragma unroll
        for (int nf = 0; nf < 8; nf++) {
            rm0 = fmaxf(rm0, fmaxf(sacc[nf][0], sacc[nf][1]));
            rm1 = fmaxf(rm1, fmaxf(sacc[nf][2], sacc[nf][3]));
        }
        rm0 = fmaxf(rm0, __shfl_xor_sync(0xffffffffu, rm0, 1));
        rm0 = fmaxf(rm0, __shfl_xor_sync(0xffffffffu, rm0, 2));
        rm1 = fmaxf(rm1, __shfl_xor_sync(0xffffffffu, rm1, 1));
        rm1 = fmaxf(rm1, __shfl_xor_sync(0xffffffffu, rm1, 2));
        float nm0 = fmaxf(m0, rm0), nm1 = fmaxf(m1, rm1);
        float corr0 = __expf(m0 - nm0), corr1 = __expf(m1 - nm1);
        float rs0 = 0.f, rs1 = 0.f;
        #pragma unroll
        for (int nf = 0; nf < 8; nf++) {
            float p0 = __expf(sacc[nf][0] - nm0);
            float p1 = __expf(sacc[nf][1] - nm0);
            float p2 = __expf(sacc[nf][2] - nm1);
            float p3 = __expf(sacc[nf][3] - nm1);
            rs0 += p0 + p1; rs1 += p2 + p3;
            sacc[nf][0] = p0; sacc[nf][1] = p1;
            sacc[nf][2] = p2; sacc[nf][3] = p3;
        }
        rs0 += __shfl_xor_sync(0xffffffffu, rs0, 1);
        rs0 += __shfl_xor_sync(0xffffffffu, rs0, 2);
        rs1 += __shfl_xor_sync(0xffffffffu, rs1, 1);
        rs1 += __shfl_xor_sync(0xffffffffu, rs1, 2);
        l0 = l0 * corr0 + rs0;  m0 = nm0;
        l1 = l1 * corr1 + rs1;  m1 = nm1;
        #pragma unroll
        for (int nf = 0; nf < 8; nf++) {
            oacc[nf][0] *= corr0; oacc[nf][1] *= corr0;
            oacc[nf][2] *= corr1; oacc[nf][3] *= corr1;
        }

        #pragma unroll
        for (int nf = 0; nf < 8; nf++) {
            int cc = nf * 8 + 2 * tig;
            float ph, pl;
            ph = rtf32(sacc[nf][0]); pl = rtf32(sacc[nf][0] - ph);
            Ph[prow0 + cc] = ph; Pl[prow0 + cc] = pl;
            ph = rtf32(sacc[nf][1]); pl = rtf32(sacc[nf][1] - ph);
            Ph[prow0 + cc + 1] = ph; Pl[prow0 + cc + 1] = pl;
            ph = rtf32(sacc[nf][2]); pl = rtf32(sacc[nf][2] - ph);
            Ph[prow1 + cc] = ph; Pl[prow1 + cc] = pl;
            ph = rtf32(sacc[nf][3]); pl = rtf32(sacc[nf][3] - ph);
            Ph[prow1 + cc + 1] = ph; Pl[prow1 + cc + 1] = pl;
        }
        __syncwarp();

        #pragma unroll
        for (int kf = 0; kf < 8; kf++) {
            uint32_t ah[4], al[4];
            int c = kf * 8 + tig;
            ah[0] = __float_as_uint(Ph[prow0 + c]);
            ah[1] = __float_as_uint(Ph[prow1 + c]);
            ah[2] = __float_as_uint(Ph[prow0 + c + 4]);
            ah[3] = __float_as_uint(Ph[prow1 + c + 4]);
            al[0] = __float_as_uint(Pl[prow0 + c]);
            al[1] = __float_as_uint(Pl[prow1 + c]);
            al[2] = __float_as_uint(Pl[prow0 + c + 4]);
            al[3] = __float_as_uint(Pl[prow1 + c + 4]);
            const int vr0 = (kf * 8 + tig) * 72;
            const int vr1 = (kf * 8 + tig + 4) * 72;
            #pragma unroll
            for (int nf = 0; nf < 8; nf++) {
                int n = nf * 8 + grp;
                uint32_t b0h = __float_as_uint(Vh[vr0 + n]);
                uint32_t b1h = __float_as_uint(Vh[vr1 + n]);
                uint32_t b0l = __float_as_uint(Vl[vr0 + n]);
                uint32_t b1l = __float_as_uint(Vl[vr1 + n]);
                mma_tf32_b(oacc[nf], ah, b0h, b1h);
                mma_tf32_b(oacc[nf], ah, b0l, b1l);
                mma_tf32_b(oacc[nf], al, b0h, b1h);
            }
        }
    }

    const float inv0 = 1.0f / l0, inv1 = 1.0f / l1;
    const size_t ob0 = (tokbase + row0g) * DMODEL + hh * 64;
    const size_t ob1 = (tokbase + row1g) * DMODEL + hh * 64;
    #pragma unroll
    for (int nf = 0; nf < 8; nf++) {
        int cc = nf * 8 + 2 * tig;
        o[ob0 + cc]     = oacc[nf][0] * inv0;
        o[ob0 + cc + 1] = oacc[nf][1] * inv0;
        o[ob1 + cc]     = oacc[nf][2] * inv1;
        o[ob1 + cc + 1] = oacc[nf][3] * inv1;
    }
}

// ---------------------------------------------------------------------------
// Host orchestration (graph-capturable: kernel launches only)
// ---------------------------------------------------------------------------
extern "C" void kernel_launch(void* const* d_in, const int* in_sizes, int n_in,
                              void* d_out, int out_size) {
    const int*   idx   = (const int*)d_in[0];
    const float* wte   = (const float*)d_in[1];
    const float* wpe   = (const float*)d_in[2];
    const float* ln1_w = (const float*)d_in[3];
    const float* ln1_b = (const float*)d_in[4];
    const float* Wqkv  = (const float*)d_in[5];
    const float* bqkv  = (const float*)d_in[6];
    const float* Wproj = (const float*)d_in[7];
    const float* bproj = (const float*)d_in[8];
    const float* ln2_w = (const float*)d_in[9];
    const float* ln2_b = (const float*)d_in[10];
    const float* Wfc   = (const float*)d_in[11];
    const float* bfc   = (const float*)d_in[12];
    const float* Wfc2  = (const float*)d_in[13];
    const float* bfc2  = (const float*)d_in[14];
    const float* lnf_w = (const float*)d_in[15];
    const float* lnf_b = (const float*)d_in[16];
    float* out = (float*)d_out;

    float *x, *h, *qkv, *o, *ff;
    cudaGetSymbolAddress((void**)&x,   g_x);
    cudaGetSymbolAddress((void**)&h,   g_h);
    cudaGetSymbolAddress((void**)&qkv, g_qkv);
    cudaGetSymbolAddress((void**)&o,   g_o);
    cudaGetSymbolAddress((void**)&ff,  g_ff);

    cudaFuncSetAttribute(attn_mma_kernel,
                         cudaFuncAttributeMaxDynamicSharedMemorySize, ATTN_SMEM);
    cudaFuncSetAttribute(wgemm_kernel<false, EPI_BIAS>,
                         cudaFuncAttributeMaxDynamicSharedMemorySize, WGEMM_SMEM);
    cudaFuncSetAttribute(wgemm_kernel<false, EPI_GELU>,
                         cudaFuncAttributeMaxDynamicSharedMemorySize, WGEMM_SMEM);
    cudaFuncSetAttribute(wgemm_kernel<true, EPI_NONE>,
                         cudaFuncAttributeMaxDynamicSharedMemorySize, WGEMM_SMEM);

    embed_kernel<<<(NTOK * DMODEL) / 256, 256>>>(idx, wte, wpe, x);

    for (int l = 0; l < NLAYER; l++) {
        const float* wq  = Wqkv  + (size_t)l * DMODEL * 3 * DMODEL;
        const float* bq  = bqkv  + (size_t)l * 3 * DMODEL;
        const float* wp  = Wproj + (size_t)l * DMODEL * DMODEL;
        const float* bp  = bproj + (size_t)l * DMODEL;
        const float* wf1 = Wfc   + (size_t)l * DMODEL * FFDIM;
        const float* bf1 = bfc   + (size_t)l * FFDIM;
        const float* wf2 = Wfc2  + (size_t)l * FFDIM * DMODEL;
        const float* bf2 = bfc2  + (size_t)l * DMODEL;

        ln_kernel<<<NTOK, 256>>>(x, ln1_w + l * DMODEL, ln1_b + l * DMODEL, h);

        wgemm_kernel<false, EPI_BIAS><<<dim3(NTOK / 128, (3 * DMODEL) / 256), 256, WGEMM_SMEM>>>(
            h, wq, bq, nullptr, qkv, NTOK, 3 * DMODEL, DMODEL);

        attn_mma_kernel<<<dim3(SEQ / 64, NHEAD, NTOK / SEQ), 128, ATTN_SMEM>>>(qkv, o);

        mma_gemm_kernel<EPI_RES><<<dim3(NTOK / 128, DMODEL / 128), 256>>>(
            o, wp, bp, x, x, NTOK, DMODEL, DMODEL);

        ln_kernel<<<NTOK, 256>>>(x, ln2_w + l * DMODEL, ln2_b + l * DMODEL, h);

        wgemm_kernel<false, EPI_GELU><<<dim3(NTOK / 128, FFDIM / 256), 256, WGEMM_SMEM>>>(
            h, wf1, bf1, nullptr, ff, NTOK, FFDIM, DMODEL);

        mma_gemm_kernel<EPI_RES><<<dim3(NTOK / 128, DMODEL / 128), 256>>>(
            ff, wf2, bf2, x, x, NTOK, DMODEL, FFDIM);
    }

    ln_kernel<<<NTOK, 256>>>(x, lnf_w, lnf_b, h);

    // logits = h @ wte^T  [4096, 50257]
    wgemm_kernel<true, EPI_NONE><<<dim3(NTOK / 128, (VOCAB + 255) / 256), 256, WGEMM_SMEM>>>(
        h, wte, nullptr, nullptr, out, NTOK, VOCAB, DMODEL);
}

// round 11
// speedup vs baseline: 2.7166x; 1.0517x over previous
#include <cuda_runtime.h>
#include <math.h>
#include <cstdint>

// ---------------------------------------------------------------------------
// GPT forward. GEMMs + attention via warp-level tf32 mma.sync (sm_80 PTX --
// compiles on plain sm_103 target; tcgen05 rejected by this harness's ptxas).
// R8 change (untested -- R9/R10 lost to container infra): all tf32 rounding
// hoisted to producers (LN/attn/GELU outputs, weights pre-rounded once into
// scratch) -> GEMM inner loops are pure LDS+MMA.
// Bit-identical numerics to the 3810us kernel (each value rounded once, rna,
// same dataflow).
// B=2, S=2048 (4096 tokens), D=512, H=8, HD=64, FF=2048, L=4, V=50257.
// ---------------------------------------------------------------------------

#define NTOK   4096
#define DMODEL 512
#define NLAYER 4
#define NHEAD  8
#define HDIM   64
#define FFDIM  2048
#define SEQ    2048
#define VOCAB  50257

__device__ float g_x[NTOK * DMODEL];
__device__ float g_h[NTOK * DMODEL];
__device__ float g_qkv[NTOK * 3 * DMODEL];
__device__ float g_o[NTOK * DMODEL];
__device__ float g_ff[NTOK * FFDIM];
// Pre-rounded (tf32) weights scratch: Wqkv | Wproj | Wfc | Wfc2 | wte
#define WOFF_QKV  0
#define WOFF_PROJ 3145728
#define WOFF_FC   4194304
#define WOFF_FC2  8388608
#define WOFF_WTE  12582912
#define WTOTAL    38314496
__device__ float g_w[WTOTAL];

// ---------------------------------------------------------------------------
// tf32 / cp.async helpers
// ---------------------------------------------------------------------------
__device__ __forceinline__ float rtf32(float x) {
    uint32_t u;
    asm("cvt.rna.tf32.f32 %0, %1;" : "=r"(u) : "f"(x));
    return __uint_as_float(u);
}

__device__ __forceinline__ float4 rtf32x4(float4 v) {
    uint32_t a, b, c, d;
    asm("cvt.rna.tf32.f32 %0, %1;" : "=r"(a) : "f"(v.x));
    asm("cvt.rna.tf32.f32 %0, %1;" : "=r"(b) : "f"(v.y));
    asm("cvt.rna.tf32.f32 %0, %1;" : "=r"(c) : "f"(v.z));
    asm("cvt.rna.tf32.f32 %0, %1;" : "=r"(d) : "f"(v.w));
    v.x = __uint_as_float(a); v.y = __uint_as_float(b);
    v.z = __uint_as_float(c); v.w = __uint_as_float(d);
    return v;
}

__device__ __forceinline__ void mma_tf32(float* d, const uint32_t* a,
                                         const uint32_t* b) {
    asm volatile(
        "mma.sync.aligned.m16n8k8.row.col.f32.tf32.tf32.f32 "
        "{%0,%1,%2,%3}, {%4,%5,%6,%7}, {%8,%9}, {%0,%1,%2,%3};"
        : "+f"(d[0]), "+f"(d[1]), "+f"(d[2]), "+f"(d[3])
        : "r"(a[0]), "r"(a[1]), "r"(a[2]), "r"(a[3]),
          "r"(b[0]), "r"(b[1]));
}

__device__ __forceinline__ void mma_tf32_b(float* d, const uint32_t* a,
                                           uint32_t b0, uint32_t b1) {
    asm volatile(
        "mma.sync.aligned.m16n8k8.row.col.f32.tf32.tf32.f32 "
        "{%0,%1,%2,%3}, {%4,%5,%6,%7}, {%8,%9}, {%0,%1,%2,%3};"
        : "+f"(d[0]), "+f"(d[1]), "+f"(d[2]), "+f"(d[3])
        : "r"(a[0]), "r"(a[1]), "r"(a[2]), "r"(a[3]),
          "r"(b0), "r"(b1));
}

__device__ __forceinline__ uint32_t cvsm(const void* p) {
    return (uint32_t)__cvta_generic_to_shared(p);
}
#define CP_A16(dst, src) \
    asm volatile("cp.async.ca.shared.global [%0], [%1], 16;" \
                 :: "r"(dst), "l"(src))
#define CP_A16Z(dst, src, sb) \
    asm volatile("cp.async.ca.shared.global [%0], [%1], 16, %2;" \
                 :: "r"(dst), "l"(src), "r"(sb))
#define CP_COMMIT() asm volatile("cp.async.commit_group;")
#define CP_WAIT(n)  asm volatile("cp.async.wait_group %0;" :: "n"(n))

// ---------------------------------------------------------------------------
// Pre-round copy: dst[i] = tf32(src[i]), float4 grid-stride
// ---------------------------------------------------------------------------
__global__ void rcopy_kernel(const float* __restrict__ src,
                             float* __restrict__ dst, int n4) {
    int i = blockIdx.x * 256 + threadIdx.x;
    int stride = gridDim.x * 256;
    for (; i < n4; i += stride) {
        float4 v = *(const float4*)(src + (size_t)i * 4);
        *(float4*)(dst + (size_t)i * 4) = rtf32x4(v);
    }
}

// ---------------------------------------------------------------------------
// Embedding
// ---------------------------------------------------------------------------
__global__ void embed_kernel(const int* __restrict__ idx,
                             const float* __restrict__ wte,
                             const float* __restrict__ wpe,
                             float* __restrict__ x) {
    int i = blockIdx.x * 256 + threadIdx.x;
    int tok = i >> 9;
    int d   = i & 511;
    int s   = tok & (SEQ - 1);
    x[i] = wte[(size_t)idx[tok] * DMODEL + d] + wpe[s * DMODEL + d];
}

// ---------------------------------------------------------------------------
// LayerNorm over last dim (512); output tf32-rounded (consumed only as GEMM A)
// ---------------------------------------------------------------------------
__global__ void ln_kernel(const float* __restrict__ x,
                          const float* __restrict__ w,
                          const float* __restrict__ b,
                          float* __restrict__ out) {
    int row = blockIdx.x;
    int tid = threadIdx.x;
    const float* xr = x + (size_t)row * DMODEL;
    float v0 = xr[tid];
    float v1 = xr[tid + 256];
    float s  = v0 + v1;
    float sq = v0 * v0 + v1 * v1;
    #pragma unroll
    for (int off = 16; off >= 1; off >>= 1) {
        s  += __shfl_xor_sync(0xffffffffu, s,  off);
        sq += __shfl_xor_sync(0xffffffffu, sq, off);
    }
    __shared__ float ss[8], ssq[8];
    int warp = tid >> 5, lane = tid & 31;
    if (lane == 0) { ss[warp] = s; ssq[warp] = sq; }
    __syncthreads();
    float ts = 0.f, tq = 0.f;
    #pragma unroll
    for (int wI = 0; wI < 8; wI++) { ts += ss[wI]; tq += ssq[wI]; }
    float mean = ts * (1.0f / DMODEL);
    float var  = tq * (1.0f / DMODEL) - mean * mean;
    float rstd = rsqrtf(var + 1e-5f);
    float* outr = out + (size_t)row * DMODEL;
    outr[tid]       = rtf32((v0 - mean) * rstd * w[tid]       + b[tid]);
    outr[tid + 256] = rtf32((v1 - mean) * rstd * w[tid + 256] + b[tid + 256]);
}

#define EPI_BIAS 0
#define EPI_GELU 1
#define EPI_RES  2
#define EPI_NONE 3

// ---------------------------------------------------------------------------
// WIDE tf32 GEMM: CTA 128x256, 8 warps (2m x 4n) at 64x64 each, K chunk 32,
// cp.async double-buffered. Operands are PRE-ROUNDED tf32 -> plain LDS.
//   TRANSB=false: B [K,N] row-major, N % 256 == 0.  (QKV, FC1)
//   TRANSB=true : B [N,K] row-major, N guarded.     (lm_head)
// EPI_GELU output is tf32-rounded (feeds FC2's A operand).
// ---------------------------------------------------------------------------
#define WGEMM_SMEM 110592

template<bool TRANSB, int EPI>
__global__ __launch_bounds__(256)
void wgemm_kernel(const float* __restrict__ A, const float* __restrict__ B,
                  const float* __restrict__ bias, const float* __restrict__ R,
                  float* __restrict__ C, int M, int N, int K) {
    extern __shared__ float wsm[];
    float* const As0 = wsm;
    float* const As1 = wsm + 4608;
    float* const Bs0 = wsm + 9216;
    float* const Bs1 = wsm + 18432;

    const int tid  = threadIdx.x;
    const int lane = tid & 31;
    const int warp = tid >> 5;
    const int wm   = warp & 1;
    const int wn   = warp >> 1;
    const int grp  = lane >> 2;
    const int tig  = lane & 3;
    const int m0   = blockIdx.x * 128;
    const int n0   = blockIdx.y * 256;

    float acc[4][8][4];
    #pragma unroll
    for (int i = 0; i < 4; i++)
        #pragma unroll
        for (int j = 0; j < 8; j++)
            #pragma unroll
            for (int r = 0; r < 4; r++) acc[i][j][r] = 0.f;

    const int nchunk = K >> 5;

    auto stage = [&](int ch, float* As, float* Bs) {
        {
            const int row = tid >> 1;
            const int f4b = (tid & 1) * 4;
            const float* g = A + (size_t)(m0 + row) * K + ch * 32 + f4b * 4;
            uint32_t s = cvsm(&As[row * 36 + f4b * 4]);
            #pragma unroll
            for (int u = 0; u < 4; u++)
                CP_A16(s + u * 16, g + u * 4);
        }
        if (!TRANSB) {
            const int n4  = tid & 31;
            const int kr0 = tid >> 5;
            #pragma unroll
            for (int u = 0; u < 4; u++) {
                int kr = kr0 + u * 8;
                const float* g = B + (size_t)(ch * 32 + kr) * N + n0 + n4 * 4;
                uint32_t s = cvsm(&Bs[kr * 264 + n4 * 4]);
                CP_A16(s, g);
                CP_A16(s + 512, g + 128);
            }
        } else {
            #pragma unroll
            for (int h = 0; h < 2; h++) {
                int nr = (tid >> 1) + h * 128;
                int gn = n0 + nr;
                uint32_t sb  = (gn < N) ? 16u : 0u;
                int      gnc = (gn < N) ? gn : 0;
                const int f4b = (tid & 1) * 4;
                const float* g = B + (size_t)gnc * K + ch * 32 + f4b * 4;
                uint32_t s = cvsm(&Bs[nr * 36 + f4b * 4]);
                #pragma unroll
                for (int u = 0; u < 4; u++)
                    CP_A16Z(s + u * 16, g + u * 4, sb);
            }
        }
    };

    stage(0, As0, Bs0);
    CP_COMMIT();

    #pragma unroll 1
    for (int ch = 0; ch < nchunk; ch++) {
        const int b = ch & 1;
        float* As = b ? As1 : As0;
        float* Bs = b ? Bs1 : Bs0;
        __syncthreads();
        if (ch + 1 < nchunk) {
            stage(ch + 1, b ? As0 : As1, b ? Bs0 : Bs1);
            CP_COMMIT();
            CP_WAIT(1);
        } else {
            CP_WAIT(0);
        }
        __syncthreads();

        #pragma unroll
        for (int ks = 0; ks < 4; ks++) {
            const int c = ks * 8 + tig;
            uint32_t af[4][4];
            #pragma unroll
            for (int mf = 0; mf < 4; mf++) {
                int r = wm * 64 + mf * 16 + grp;
                af[mf][0] = __float_as_uint(As[r * 36 + c]);
                af[mf][1] = __float_as_uint(As[(r + 8) * 36 + c]);
                af[mf][2] = __float_as_uint(As[r * 36 + c + 4]);
                af[mf][3] = __float_as_uint(As[(r + 8) * 36 + c + 4]);
            }
            uint32_t bf[8][2];
            #pragma unroll
            for (int nf = 0; nf < 8; nf++) {
                int n = wn * 64 + nf * 8 + grp;
                if (!TRANSB) {
                    bf[nf][0] = __float_as_uint(Bs[c * 264 + n]);
                    bf[nf][1] = __float_as_uint(Bs[(c + 4) * 264 + n]);
                } else {
                    bf[nf][0] = __float_as_uint(Bs[n * 36 + c]);
                    bf[nf][1] = __float_as_uint(Bs[n * 36 + c + 4]);
                }
            }
            #pragma unroll
            for (int mf = 0; mf < 4; mf++)
                #pragma unroll
                for (int nf = 0; nf < 8; nf++)
                    mma_tf32(acc[mf][nf], af[mf], bf[nf]);
        }
    }

    #pragma unroll
    for (int mf = 0; mf < 4; mf++) {
        #pragma unroll
        for (int half = 0; half < 2; half++) {
            int row = m0 + wm * 64 + mf * 16 + grp + half * 8;
            size_t ro = (size_t)row * N;
            #pragma unroll
            for (int nf = 0; nf < 8; nf++) {
                int col = n0 + wn * 64 + nf * 8 + tig * 2;
                float v0 = acc[mf][nf][half * 2 + 0];
                float v1 = acc[mf][nf][half * 2 + 1];
                if (EPI != EPI_NONE) { v0 += bias[col]; v1 += bias[col + 1]; }
                if (EPI == EPI_GELU) {
                    v0 = rtf32(0.5f * v0 * (1.0f + erff(v0 * 0.70710678118654752f)));
                    v1 = rtf32(0.5f * v1 * (1.0f + erff(v1 * 0.70710678118654752f)));
                }
                if (EPI == EPI_RES) { v0 += R[ro + col]; v1 += R[ro + col + 1]; }
                if (!TRANSB) {
                    C[ro + col]     = v0;
                    C[ro + col + 1] = v1;
                } else {
                    if (col < N)     C[ro + col]     = v0;
                    if (col + 1 < N) C[ro + col + 1] = v1;
                }
            }
        }
    }
}

// ---------------------------------------------------------------------------
// NARROW tf32 GEMM: CTA 128x128, N=512 GEMMs. Operands pre-rounded.
// ---------------------------------------------------------------------------
template<int EPI>
__global__ __launch_bounds__(256)
void mma_gemm_kernel(const float* __restrict__ A, const float* __restrict__ B,
                     const float* __restrict__ bias, const float* __restrict__ R,
                     float* __restrict__ C, int M, int N, int K) {
    __shared__ float As[32][136];
    __shared__ float Bs[32][136];

    const int tid  = threadIdx.x;
    const int lane = tid & 31;
    const int wid  = tid >> 5;
    const int wm   = wid & 1;
    const int wn   = wid >> 1;
    const int m0   = blockIdx.x * 128;
    const int n0   = blockIdx.y * 128;

    const int tig  = lane & 3;
    const int grp  = lane >> 2;

    float acc[4][4][4];
    #pragma unroll
    for (int i = 0; i < 4; i++)
        #pragma unroll
        for (int j = 0; j < 4; j++)
            #pragma unroll
            for (int r = 0; r < 4; r++) acc[i][j][r] = 0.f;

    const int st_r  = tid >> 1;
    const int st_k0 = (tid & 1) * 16;
    const int bq_n  = (tid & 31) * 4;
    const int bq_k  = tid >> 5;

    const int nchunk = K >> 5;

    float4 pa[4], pb[4];

    {
        const float* Ap = A + (size_t)(m0 + st_r) * K + st_k0;
        #pragma unroll
        for (int u = 0; u < 4; u++)
            pa[u] = *(const float4*)(Ap + u * 4);
        #pragma unroll
        for (int u = 0; u < 4; u++)
            pb[u] = *(const float4*)(B + (size_t)(u * 8 + bq_k) * N + n0 + bq_n);
    }

    #pragma unroll 1
    for (int ch = 0; ch < nchunk; ch++) {
        __syncthreads();
        #pragma unroll
        for (int u = 0; u < 4; u++) {
            float4 av = pa[u];
            int k = st_k0 + u * 4;
            As[k + 0][st_r] = av.x;
            As[k + 1][st_r] = av.y;
            As[k + 2][st_r] = av.z;
            As[k + 3][st_r] = av.w;
            *(float4*)&Bs[u * 8 + bq_k][bq_n] = pb[u];
        }
        __syncthreads();

        if (ch + 1 < nchunk) {
            const int k0 = (ch + 1) * 32;
            const float* Ap = A + (size_t)(m0 + st_r) * K + k0 + st_k0;
            #pragma unroll
            for (int u = 0; u < 4; u++)
                pa[u] = *(const float4*)(Ap + u * 4);
            #pragma unroll
            for (int u = 0; u < 4; u++)
                pb[u] = *(const float4*)(B + (size_t)(k0 + u * 8 + bq_k) * N + n0 + bq_n);
        }

        #pragma unroll
        for (int ks = 0; ks < 4; ks++) {
            const int c = ks * 8 + tig;
            uint32_t af[4][4];
            #pragma unroll
            for (int mf = 0; mf < 4; mf++) {
                int r = wm * 64 + mf * 16 + grp;
                af[mf][0] = __float_as_uint(As[c][r]);
                af[mf][1] = __float_as_uint(As[c][r + 8]);
                af[mf][2] = __float_as_uint(As[c + 4][r]);
                af[mf][3] = __float_as_uint(As[c + 4][r + 8]);
            }
            uint32_t bf[4][2];
            #pragma unroll
            for (int nf = 0; nf < 4; nf++) {
                int n = wn * 32 + nf * 8 + grp;
                bf[nf][0] = __float_as_uint(Bs[c][n]);
                bf[nf][1] = __float_as_uint(Bs[c + 4][n]);
            }
            #pragma unroll
            for (int mf = 0; mf < 4; mf++)
                #pragma unroll
                for (int nf = 0; nf < 4; nf++)
                    mma_tf32(acc[mf][nf], af[mf], bf[nf]);
        }
    }

    #pragma unroll
    for (int mf = 0; mf < 4; mf++) {
        #pragma unroll
        for (int half = 0; half < 2; half++) {
            int row = m0 + wm * 64 + mf * 16 + grp + half * 8;
            size_t ro = (size_t)row * N;
            #pragma unroll
            for (int nf = 0; nf < 4; nf++) {
                int col = n0 + wn * 32 + nf * 8 + tig * 2;
                float v0 = acc[mf][nf][half * 2 + 0];
                float v1 = acc[mf][nf][half * 2 + 1];
                v0 += bias[col]; v1 += bias[col + 1];
                if (EPI == EPI_RES) { v0 += R[ro + col]; v1 += R[ro + col + 1]; }
                C[ro + col]     = v0;
                C[ro + col + 1] = v1;
            }
        }
    }
}

// ---------------------------------------------------------------------------
// Causal flash attention via tf32 mma.sync (passing R6/R8).
// Output o is tf32-rounded (consumed only as proj's A operand).
// ---------------------------------------------------------------------------
#define ATTN_SMEM 89088   // 22272 floats

__global__ __launch_bounds__(128)
void attn_mma_kernel(const float* __restrict__ qkv, float* __restrict__ o) {
    extern __shared__ float sm[];
    float* Ks = sm;              // [64][68]
    float* Vh = sm + 4352;       // [64][72]
    float* Vl = sm + 8960;       // [64][72]
    float* Ph = sm + 13568;      // [64][68]
    float* Pl = sm + 17920;      // [64][68]

    const int tid  = threadIdx.x;
    const int lane = tid & 31;
    const int warp = tid >> 5;
    const int grp  = lane >> 2;
    const int tig  = lane & 3;
    const int qb = blockIdx.x, hh = blockIdx.y, bb = blockIdx.z;
    const int q0 = qb * 64;
    const size_t tokbase = (size_t)bb * SEQ;

    #pragma unroll
    for (int u = 0; u < 8; u++) {
        int idx = u * 128 + tid;
        int r = idx >> 4;
        int c = (idx & 15) << 2;
        const float* src = qkv + (tokbase + q0 + r) * 1536 + hh * 64 + c;
        *(float4*)&Ks[r * 68 + c] = *(const float4*)src;
    }
    __syncthreads();

    uint32_t qa[8][4];
    {
        const int r0 = (warp * 16 + grp) * 68;
        const int r1 = r0 + 8 * 68;
        #pragma unroll
        for (int kf = 0; kf < 8; kf++) {
            int c = kf * 8 + tig;
            qa[kf][0] = __float_as_uint(rtf32(Ks[r0 + c]));
            qa[kf][1] = __float_as_uint(rtf32(Ks[r1 + c]));
            qa[kf][2] = __float_as_uint(rtf32(Ks[r0 + c + 4]));
            qa[kf][3] = __float_as_uint(rtf32(Ks[r1 + c + 4]));
        }
    }

    float m0 = -1e30f, m1 = -1e30f, l0 = 0.f, l1 = 0.f;
    float oacc[8][4];
    #pragma unroll
    for (int nf = 0; nf < 8; nf++)
        #pragma unroll
        for (int c = 0; c < 4; c++) oacc[nf][c] = 0.f;

    const int prow0 = (warp * 16 + grp) * 68;
    const int prow1 = prow0 + 8 * 68;
    const int row0g = q0 + warp * 16 + grp;
    const int row1g = row0g + 8;

    #pragma unroll 1
    for (int kb = 0; kb <= qb; kb++) {
        const int k0 = kb * 64;
        __syncthreads();
        #pragma unroll
        for (int u = 0; u < 8; u++) {
            int idx = u * 128 + tid;
            int r = idx >> 4;
            int c = (idx & 15) << 2;
            const float* kp = qkv + (tokbase + k0 + r) * 1536 + 512 + hh * 64 + c;
            *(float4*)&Ks[r * 68 + c] = rtf32x4(*(const float4*)kp);
            const float* vp = qkv + (tokbase + k0 + r) * 1536 + 1024 + hh * 64 + c;
            float4 v  = *(const float4*)vp;
            float4 vh = rtf32x4(v);
            float4 vl;
            vl.x = v.x - vh.x; vl.y = v.y - vh.y;
            vl.z = v.z - vh.z; vl.w = v.w - vh.w;
            vl = rtf32x4(vl);
            *(float4*)&Vh[r * 72 + c] = vh;
            *(float4*)&Vl[r * 72 + c] = vl;
        }
        __syncthreads();

        float sacc[8][4];
        #pragma unroll
        for (int nf = 0; nf < 8; nf++) {
            #pragma unroll
            for (int c = 0; c < 4; c++) sacc[nf][c] = 0.f;
            const int kb_row = (nf * 8 + grp) * 68;
            #pragma unroll
            for (int kf = 0; kf < 8; kf++) {
                uint32_t b0 = __float_as_uint(Ks[kb_row + kf * 8 + tig]);
                uint32_t b1 = __float_as_uint(Ks[kb_row + kf * 8 + tig + 4]);
                mma_tf32_b(sacc[nf], qa[kf], b0, b1);
            }
        }

        const float scale = 0.125f;
        #pragma unroll
        for (int nf = 0; nf < 8; nf++) {
            int colb = k0 + nf * 8 + 2 * tig;
            sacc[nf][0] = (colb     > row0g) ? -1e30f : sacc[nf][0] * scale;
            sacc[nf][1] = (colb + 1 > row0g) ? -1e30f : sacc[nf][1] * scale;
            sacc[nf][2] = (colb     > row1g) ? -1e30f : sacc[nf][2] * scale;
            sacc[nf][3] = (colb + 1 > row1g) ? -1e30f : sacc[nf][3] * scale;
        }

        float rm0 = -1e30f, rm1 = -1e30f;
        #pragma unroll
        for (int nf = 0; nf < 8; nf++) {
            rm0 = fmaxf(rm0, fmaxf(sacc[nf][0], sacc[nf][1]));
            rm1 = fmaxf(rm1, fmaxf(sacc[nf][2], sacc[nf][3]));
        }
        rm0 = fmaxf(rm0, __shfl_xor_sync(0xffffffffu, rm0, 1));
        rm0 = fmaxf(rm0, __shfl_xor_sync(0xffffffffu, rm0, 2));
        rm1 = fmaxf(rm1, __shfl_xor_sync(0xffffffffu, rm1, 1));
        rm1 = fmaxf(rm1, __shfl_xor_sync(0xffffffffu, rm1, 2));
        float nm0 = fmaxf(m0, rm0), nm1 = fmaxf(m1, rm1);
        float corr0 = __expf(m0 - nm0), corr1 = __expf(m1 - nm1);
        float rs0 = 0.f, rs1 = 0.f;
        #pragma unroll
        for (int nf = 0; nf < 8; nf++) {
            float p0 = __expf(sacc[nf][0] - nm0);
            float p1 = __expf(sacc[nf][1] - nm0);
            float p2 = __expf(sacc[nf][2] - nm1);
            float p3 = __expf(sacc[nf][3] - nm1);
            rs0 += p0 + p1; rs1 += p2 + p3;
            sacc[nf][0] = p0; sacc[nf][1] = p1;
            sacc[nf][2] = p2; sacc[nf][3] = p3;
        }
        rs0 += __shfl_xor_sync(0xffffffffu, rs0, 1);
        rs0 += __shfl_xor_sync(0xffffffffu, rs0, 2);
        rs1 += __shfl_xor_sync(0xffffffffu, rs1, 1);
        rs1 += __shfl_xor_sync(0xffffffffu, rs1, 2);
        l0 = l0 * corr0 + rs0;  m0 = nm0;
        l1 = l1 * corr1 + rs1;  m1 = nm1;
        #pragma unroll
        for (int nf = 0; nf < 8; nf++) {
            oacc[nf][0] *= corr0; oacc[nf][1] *= corr0;
            oacc[nf][2] *= corr1; oacc[nf][3] *= corr1;
        }

        #pragma unroll
        for (int nf = 0; nf < 8; nf++) {
            int cc = nf * 8 + 2 * tig;
            float ph, pl;
            ph = rtf32(sacc[nf][0]); pl = rtf32(sacc[nf][0] - ph);
            Ph[prow0 + cc] = ph; Pl[prow0 + cc] = pl;
            ph = rtf32(sacc[nf][1]); pl = rtf32(sacc[nf][1] - ph);
            Ph[prow0 + cc + 1] = ph; Pl[prow0 + cc + 1] = pl;
            ph = rtf32(sacc[nf][2]); pl = rtf32(sacc[nf][2] - ph);
            Ph[prow1 + cc] = ph; Pl[prow1 + cc] = pl;
            ph = rtf32(sacc[nf][3]); pl = rtf32(sacc[nf][3] - ph);
            Ph[prow1 + cc + 1] = ph; Pl[prow1 + cc + 1] = pl;
        }
        __syncwarp();

        #pragma unroll
        for (int kf = 0; kf < 8; kf++) {
            uint32_t ah[4], al[4];
            int c = kf * 8 + tig;
            ah[0] = __float_as_uint(Ph[prow0 + c]);
            ah[1] = __float_as_uint(Ph[prow1 + c]);
            ah[2] = __float_as_uint(Ph[prow0 + c + 4]);
            ah[3] = __float_as_uint(Ph[prow1 + c + 4]);
            al[0] = __float_as_uint(Pl[prow0 + c]);
            al[1] = __float_as_uint(Pl[prow1 + c]);
            al[2] = __float_as_uint(Pl[prow0 + c + 4]);
            al[3] = __float_as_uint(Pl[prow1 + c + 4]);
            const int vr0 = (kf * 8 + tig) * 72;
            const int vr1 = (kf * 8 + tig + 4) * 72;
            #pragma unroll
            for (int nf = 0; nf < 8; nf++) {
                int n = nf * 8 + grp;
                uint32_t b0h = __float_as_uint(Vh[vr0 + n]);
                uint32_t b1h = __float_as_uint(Vh[vr1 + n]);
                uint32_t b0l = __float_as_uint(Vl[vr0 + n]);
                uint32_t b1l = __float_as_uint(Vl[vr1 + n]);
                mma_tf32_b(oacc[nf], ah, b0h, b1h);
                mma_tf32_b(oacc[nf], ah, b0l, b1l);
                mma_tf32_b(oacc[nf], al, b0h, b1h);
            }
        }
    }

    const float inv0 = 1.0f / l0, inv1 = 1.0f / l1;
    const size_t ob0 = (tokbase + row0g) * DMODEL + hh * 64;
    const size_t ob1 = (tokbase + row1g) * DMODEL + hh * 64;
    #pragma unroll
    for (int nf = 0; nf < 8; nf++) {
        int cc = nf * 8 + 2 * tig;
        o[ob0 + cc]     = rtf32(oacc[nf][0] * inv0);
        o[ob0 + cc + 1] = rtf32(oacc[nf][1] * inv0);
        o[ob1 + cc]     = rtf32(oacc[nf][2] * inv1);
        o[ob1 + cc + 1] = rtf32(oacc[nf][3] * inv1);
    }
}

// ---------------------------------------------------------------------------
// Host orchestration (graph-capturable: kernel launches only)
// ---------------------------------------------------------------------------
extern "C" void kernel_launch(void* const* d_in, const int* in_sizes, int n_in,
                              void* d_out, int out_size) {
    const int*   idx   = (const int*)d_in[0];
    const float* wte   = (const float*)d_in[1];
    const float* wpe   = (const float*)d_in[2];
    const float* ln1_w = (const float*)d_in[3];
    const float* ln1_b = (const float*)d_in[4];
    const float* Wqkv  = (const float*)d_in[5];
    const float* bqkv  = (const float*)d_in[6];
    const float* Wproj = (const float*)d_in[7];
    const float* bproj = (const float*)d_in[8];
    const float* ln2_w = (const float*)d_in[9];
    const float* ln2_b = (const float*)d_in[10];
    const float* Wfc   = (const float*)d_in[11];
    const float* bfc   = (const float*)d_in[12];
    const float* Wfc2  = (const float*)d_in[13];
    const float* bfc2  = (const float*)d_in[14];
    const float* lnf_w = (const float*)d_in[15];
    const float* lnf_b = (const float*)d_in[16];
    float* out = (float*)d_out;

    float *x, *h, *qkv, *o, *ff, *w;
    cudaGetSymbolAddress((void**)&x,   g_x);
    cudaGetSymbolAddress((void**)&h,   g_h);
    cudaGetSymbolAddress((void**)&qkv, g_qkv);
    cudaGetSymbolAddress((void**)&o,   g_o);
    cudaGetSymbolAddress((void**)&ff,  g_ff);
    cudaGetSymbolAddress((void**)&w,   g_w);

    cudaFuncSetAttribute(attn_mma_kernel,
                         cudaFuncAttributeMaxDynamicSharedMemorySize, ATTN_SMEM);
    cudaFuncSetAttribute(wgemm_kernel<false, EPI_BIAS>,
                         cudaFuncAttributeMaxDynamicSharedMemorySize, WGEMM_SMEM);
    cudaFuncSetAttribute(wgemm_kernel<false, EPI_GELU>,
                         cudaFuncAttributeMaxDynamicSharedMemorySize, WGEMM_SMEM);
    cudaFuncSetAttribute(wgemm_kernel<true, EPI_NONE>,
                         cudaFuncAttributeMaxDynamicSharedMemorySize, WGEMM_SMEM);

    // Pre-round all weights into scratch (tf32, rna)
    rcopy_kernel<<<592, 256>>>(Wqkv,  w + WOFF_QKV,  NLAYER * DMODEL * 3 * DMODEL / 4);
    rcopy_kernel<<<592, 256>>>(Wproj, w + WOFF_PROJ, NLAYER * DMODEL * DMODEL / 4);
    rcopy_kernel<<<592, 256>>>(Wfc,   w + WOFF_FC,   NLAYER * DMODEL * FFDIM / 4);
    rcopy_kernel<<<592, 256>>>(Wfc2,  w + WOFF_FC2,  NLAYER * FFDIM * DMODEL / 4);
    rcopy_kernel<<<1184, 256>>>(wte,  w + WOFF_WTE,  VOCAB * DMODEL / 4);

    embed_kernel<<<(NTOK * DMODEL) / 256, 256>>>(idx, wte, wpe, x);

    for (int l = 0; l < NLAYER; l++) {
        const float* wq  = w + WOFF_QKV  + (size_t)l * DMODEL * 3 * DMODEL;
        const float* bq  = bqkv  + (size_t)l * 3 * DMODEL;
        const float* wp  = w + WOFF_PROJ + (size_t)l * DMODEL * DMODEL;
        const float* bp  = bproj + (size_t)l * DMODEL;
        const float* wf1 = w + WOFF_FC   + (size_t)l * DMODEL * FFDIM;
        const float* bf1 = bfc   + (size_t)l * FFDIM;
        const float* wf2 = w + WOFF_FC2  + (size_t)l * FFDIM * DMODEL;
        const float* bf2 = bfc2  + (size_t)l * DMODEL;

        ln_kernel<<<NTOK, 256>>>(x, ln1_w + l * DMODEL, ln1_b + l * DMODEL, h);

        wgemm_kernel<false, EPI_BIAS><<<dim3(NTOK / 128, (3 * DMODEL) / 256), 256, WGEMM_SMEM>>>(
            h, wq, bq, nullptr, qkv, NTOK, 3 * DMODEL, DMODEL);

        attn_mma_kernel<<<dim3(SEQ / 64, NHEAD, NTOK / SEQ), 128, ATTN_SMEM>>>(qkv, o);

        mma_gemm_kernel<EPI_RES><<<dim3(NTOK / 128, DMODEL / 128), 256>>>(
            o, wp, bp, x, x, NTOK, DMODEL, DMODEL);

        ln_kernel<<<NTOK, 256>>>(x, ln2_w + l * DMODEL, ln2_b + l * DMODEL, h);

        wgemm_kernel<false, EPI_GELU><<<dim3(NTOK / 128, FFDIM / 256), 256, WGEMM_SMEM>>>(
            h, wf1, bf1, nullptr, ff, NTOK, FFDIM, DMODEL);

        mma_gemm_kernel<EPI_RES><<<dim3(NTOK / 128, DMODEL / 128), 256>>>(
            ff, wf2, bf2, x, x, NTOK, DMODEL, FFDIM);
    }

    ln_kernel<<<NTOK, 256>>>(x, lnf_w, lnf_b, h);

    // logits = h @ wte_rounded^T  [4096, 50257]
    wgemm_kernel<true, EPI_NONE><<<dim3(NTOK / 128, (VOCAB + 255) / 256), 256, WGEMM_SMEM>>>(
        h, w + WOFF_WTE, nullptr, nullptr, out, NTOK, VOCAB, DMODEL);
}